// round 1
// baseline (speedup 1.0000x reference)
#include <cuda_runtime.h>

// Problem constants
#define BATCH   2
#define S_LEN   2048
#define D_MODEL 2048
#define NH      16
#define DHEAD   128
#define M_TOK   (BATCH * S_LEN)     // 4096 tokens
#define E3      (3 * NH * DHEAD)    // 6144 qkv features

// Scratch (alloc-free rule: __device__ globals)
__device__ float g_qkv[(size_t)M_TOK * E3];       // [4096, 6144]
__device__ float g_attn[(size_t)M_TOK * D_MODEL]; // [4096, 2048]

// ---------------------------------------------------------------------------
// SGEMM: C[M,N] = A[M,K] * B[N,K]^T   (both row-major, K contiguous)
// 128x128 tile, K-tile 8, 256 threads, 8x8 micro-tile per thread.
// All dims divisible by tiles for this problem (4096/6144/2048).
// ---------------------------------------------------------------------------
__global__ __launch_bounds__(256, 2)
void sgemm_nt(const float* __restrict__ A, const float* __restrict__ B,
              float* __restrict__ C, int M, int N, int K) {
    __shared__ float As[8][128];
    __shared__ float Bs[8][128];

    const int tid = threadIdx.x;
    const int bm = blockIdx.y * 128;
    const int bn = blockIdx.x * 128;

    const int lr = tid >> 1;          // 0..127
    const int lk = (tid & 1) * 4;     // 0 or 4

    const float* Aptr = A + (size_t)(bm + lr) * K + lk;
    const float* Bptr = B + (size_t)(bn + lr) * K + lk;

    const int ty = tid >> 4;          // 0..15 -> row group
    const int tx = tid & 15;          // 0..15 -> col group

    float acc[8][8];
#pragma unroll
    for (int i = 0; i < 8; i++)
#pragma unroll
        for (int j = 0; j < 8; j++) acc[i][j] = 0.0f;

    for (int k0 = 0; k0 < K; k0 += 8) {
        float4 av = *(const float4*)(Aptr + k0);
        float4 bv = *(const float4*)(Bptr + k0);
        As[lk + 0][lr] = av.x; As[lk + 1][lr] = av.y;
        As[lk + 2][lr] = av.z; As[lk + 3][lr] = av.w;
        Bs[lk + 0][lr] = bv.x; Bs[lk + 1][lr] = bv.y;
        Bs[lk + 2][lr] = bv.z; Bs[lk + 3][lr] = bv.w;
        __syncthreads();

#pragma unroll
        for (int k = 0; k < 8; k++) {
            float a[8], b[8];
            float4 a0 = *(const float4*)&As[k][ty * 8];
            float4 a1 = *(const float4*)&As[k][ty * 8 + 4];
            float4 b0 = *(const float4*)&Bs[k][tx * 8];
            float4 b1 = *(const float4*)&Bs[k][tx * 8 + 4];
            a[0]=a0.x; a[1]=a0.y; a[2]=a0.z; a[3]=a0.w;
            a[4]=a1.x; a[5]=a1.y; a[6]=a1.z; a[7]=a1.w;
            b[0]=b0.x; b[1]=b0.y; b[2]=b0.z; b[3]=b0.w;
            b[4]=b1.x; b[5]=b1.y; b[6]=b1.z; b[7]=b1.w;
#pragma unroll
            for (int i = 0; i < 8; i++)
#pragma unroll
                for (int j = 0; j < 8; j++)
                    acc[i][j] = fmaf(a[i], b[j], acc[i][j]);
        }
        __syncthreads();
    }

#pragma unroll
    for (int i = 0; i < 8; i++) {
        float* crow = C + (size_t)(bm + ty * 8 + i) * N + bn + tx * 8;
#pragma unroll
        for (int j = 0; j < 8; j += 4) {
            float4 v = make_float4(acc[i][j], acc[i][j+1], acc[i][j+2], acc[i][j+3]);
            *(float4*)(crow + j) = v;
        }
    }
}

// ---------------------------------------------------------------------------
// Flash attention, causal, fp32. One block = 64 query rows of one (b,h).
// qkv layout per token row: head h occupies cols [h*384, h*384+384):
//   [0:128)=q, [128:256)=k, [256:384)=v.
// 256 threads as (ty 0..15, tx 0..15):
//   S tile: rows ty*4+i, cols tx*4+j (4x4)
//   O tile: rows ty*4+i, cols tx*8+j (4x8)
// Dynamic smem: Qs 64x128 + Ks 64x128 + Vs 64x128 + Ps 64x64 = 112 KB
// ---------------------------------------------------------------------------
#define BM 64
#define BN 64
#define FA_SMEM ((3 * BM * DHEAD + BM * BN) * (int)sizeof(float))

__global__ __launch_bounds__(256, 1)
void flash_attn(const float* __restrict__ qkv, float* __restrict__ out) {
    extern __shared__ float sm[];
    float* Qs = sm;                       // [BM][DHEAD]
    float* Ks = Qs + BM * DHEAD;          // [BN][DHEAD]
    float* Vs = Ks + BN * DHEAD;          // [BN][DHEAD]
    float* Ps = Vs + BN * DHEAD;          // [BM][BN]

    const int tid = threadIdx.x;
    const int bh = blockIdx.y;
    const int b = bh >> 4;
    const int h = bh & 15;
    const int q0 = blockIdx.x * BM;

    const float scale = 0.08838834764831845f;  // 1/sqrt(128)
    const size_t base = (size_t)b * S_LEN * E3 + (size_t)h * 384;

    // Load Q tile (pre-scaled)
#pragma unroll
    for (int it = 0; it < (BM * DHEAD / 4) / 256; it++) {
        int i = tid + it * 256;
        int r = i >> 5, c4 = (i & 31) << 2;
        float4 v = *(const float4*)(qkv + base + (size_t)(q0 + r) * E3 + c4);
        v.x *= scale; v.y *= scale; v.z *= scale; v.w *= scale;
        *(float4*)(Qs + r * DHEAD + c4) = v;
    }

    const int ty = tid >> 4;
    const int tx = tid & 15;

    float o[4][8];
    float m_i[4], l_i[4];
#pragma unroll
    for (int i = 0; i < 4; i++) {
        m_i[i] = -1e30f; l_i[i] = 0.0f;
#pragma unroll
        for (int j = 0; j < 8; j++) o[i][j] = 0.0f;
    }

    const int nkt = q0 / BN + 1;   // causal: key tiles 0..q0/64
    for (int kb = 0; kb < nkt; kb++) {
        const int k0 = kb * BN;
        __syncthreads();   // protect Ks/Vs (prev PV) and Ps (prev PV read)
        // Load K and V tiles
#pragma unroll
        for (int it = 0; it < (BN * DHEAD / 4) / 256; it++) {
            int i = tid + it * 256;
            int r = i >> 5, c4 = (i & 31) << 2;
            const float* p = qkv + base + (size_t)(k0 + r) * E3 + c4;
            *(float4*)(Ks + r * DHEAD + c4) = *(const float4*)(p + 128);
            *(float4*)(Vs + r * DHEAD + c4) = *(const float4*)(p + 256);
        }
        __syncthreads();

        // S = Q * K^T  (4x4 per thread)
        float s[4][4];
#pragma unroll
        for (int i = 0; i < 4; i++)
#pragma unroll
            for (int j = 0; j < 4; j++) s[i][j] = 0.0f;

#pragma unroll 4
        for (int kk = 0; kk < DHEAD; kk += 4) {
            float4 qv[4], kv[4];
#pragma unroll
            for (int i = 0; i < 4; i++)
                qv[i] = *(const float4*)(Qs + (ty * 4 + i) * DHEAD + kk);
#pragma unroll
            for (int j = 0; j < 4; j++)
                kv[j] = *(const float4*)(Ks + (tx * 4 + j) * DHEAD + kk);
#pragma unroll
            for (int i = 0; i < 4; i++)
#pragma unroll
                for (int j = 0; j < 4; j++) {
                    s[i][j] = fmaf(qv[i].x, kv[j].x, s[i][j]);
                    s[i][j] = fmaf(qv[i].y, kv[j].y, s[i][j]);
                    s[i][j] = fmaf(qv[i].z, kv[j].z, s[i][j]);
                    s[i][j] = fmaf(qv[i].w, kv[j].w, s[i][j]);
                }
        }

        // Causal mask (only the diagonal tile, where k0 == q0)
        if (kb == nkt - 1) {
#pragma unroll
            for (int i = 0; i < 4; i++)
#pragma unroll
                for (int j = 0; j < 4; j++)
                    if (tx * 4 + j > ty * 4 + i) s[i][j] = -1e30f;
        }

        // Online softmax per row (reduce across tx: lanes xor 1,2,4,8)
#pragma unroll
        for (int i = 0; i < 4; i++) {
            float mx = fmaxf(fmaxf(s[i][0], s[i][1]), fmaxf(s[i][2], s[i][3]));
#pragma unroll
            for (int off = 1; off < 16; off <<= 1)
                mx = fmaxf(mx, __shfl_xor_sync(0xffffffffu, mx, off));
            float m_new = fmaxf(m_i[i], mx);
            float corr = __expf(m_i[i] - m_new);
            float rs = 0.0f;
#pragma unroll
            for (int j = 0; j < 4; j++) {
                float p = __expf(s[i][j] - m_new);
                s[i][j] = p;
                rs += p;
            }
#pragma unroll
            for (int off = 1; off < 16; off <<= 1)
                rs += __shfl_xor_sync(0xffffffffu, rs, off);
            l_i[i] = l_i[i] * corr + rs;
            m_i[i] = m_new;
#pragma unroll
            for (int j = 0; j < 8; j++) o[i][j] *= corr;
        }

        // Write P tile
#pragma unroll
        for (int i = 0; i < 4; i++)
#pragma unroll
            for (int j = 0; j < 4; j++)
                Ps[(ty * 4 + i) * BN + tx * 4 + j] = s[i][j];
        __syncthreads();

        // O += P * V   (rows ty*4+i, cols tx*8 .. tx*8+7)
#pragma unroll 4
        for (int kk = 0; kk < BN; kk++) {
            float pr[4];
#pragma unroll
            for (int i = 0; i < 4; i++) pr[i] = Ps[(ty * 4 + i) * BN + kk];
            float4 v0 = *(const float4*)(Vs + kk * DHEAD + tx * 8);
            float4 v1 = *(const float4*)(Vs + kk * DHEAD + tx * 8 + 4);
#pragma unroll
            for (int i = 0; i < 4; i++) {
                o[i][0] = fmaf(pr[i], v0.x, o[i][0]);
                o[i][1] = fmaf(pr[i], v0.y, o[i][1]);
                o[i][2] = fmaf(pr[i], v0.z, o[i][2]);
                o[i][3] = fmaf(pr[i], v0.w, o[i][3]);
                o[i][4] = fmaf(pr[i], v1.x, o[i][4]);
                o[i][5] = fmaf(pr[i], v1.y, o[i][5]);
                o[i][6] = fmaf(pr[i], v1.z, o[i][6]);
                o[i][7] = fmaf(pr[i], v1.w, o[i][7]);
            }
        }
    }

    // Epilogue: normalize and write to attn buffer [M_TOK, D_MODEL]
#pragma unroll
    for (int i = 0; i < 4; i++) {
        float inv = 1.0f / l_i[i];
        float* orow = out + (size_t)((size_t)b * S_LEN + q0 + ty * 4 + i) * D_MODEL
                          + h * DHEAD + tx * 8;
        float4 v0 = make_float4(o[i][0]*inv, o[i][1]*inv, o[i][2]*inv, o[i][3]*inv);
        float4 v1 = make_float4(o[i][4]*inv, o[i][5]*inv, o[i][6]*inv, o[i][7]*inv);
        *(float4*)(orow)     = v0;
        *(float4*)(orow + 4) = v1;
    }
}

// ---------------------------------------------------------------------------
extern "C" void kernel_launch(void* const* d_in, const int* in_sizes, int n_in,
                              void* d_out, int out_size) {
    const float* x     = (const float*)d_in[0];  // [B,S,D]
    const float* w_in  = (const float*)d_in[1];  // [3*H*DH, D]
    const float* w_out = (const float*)d_in[2];  // [D, H*DH]
    float* out = (float*)d_out;                  // [B,S,D]

    float *qkv, *attn;
    cudaGetSymbolAddress((void**)&qkv, g_qkv);
    cudaGetSymbolAddress((void**)&attn, g_attn);

    // 1) QKV projection: [4096,2048] x [6144,2048]^T -> [4096,6144]
    dim3 g1(E3 / 128, M_TOK / 128);
    sgemm_nt<<<g1, 256>>>(x, w_in, qkv, M_TOK, E3, D_MODEL);

    // 2) Causal flash attention -> [4096, 2048]
    cudaFuncSetAttribute(flash_attn, cudaFuncAttributeMaxDynamicSharedMemorySize,
                         FA_SMEM);
    dim3 g2(S_LEN / BM, BATCH * NH);
    flash_attn<<<g2, 256, FA_SMEM>>>(qkv, attn);

    // 3) Output projection: [4096,2048] x [2048,2048]^T -> [4096,2048]
    dim3 g3(D_MODEL / 128, M_TOK / 128);
    sgemm_nt<<<g3, 256>>>(attn, w_out, out, M_TOK, D_MODEL, D_MODEL);
}

// round 3
// speedup vs baseline: 1.6188x; 1.6188x over previous
#include <cuda_runtime.h>
#include <cstdint>

// Problem constants
#define BATCH   2
#define S_LEN   2048
#define D_MODEL 2048
#define NH      16
#define DHEAD   128
#define M_TOK   (BATCH * S_LEN)     // 4096 tokens
#define E3      (3 * NH * DHEAD)    // 6144 qkv features

// Scratch (alloc-free rule: __device__ globals)
__device__ float g_qkv[(size_t)M_TOK * E3];       // [4096, 6144]
__device__ float g_attn[(size_t)M_TOK * D_MODEL]; // [4096, 2048]

// ===========================================================================
// PTX helpers (generic sm_80+ features only — toolchain targets plain
// compute_103, so tcgen05/'a'-suffix features are unavailable).
// ===========================================================================
__device__ __forceinline__ uint32_t smem_u32(const void* p) {
    uint32_t a;
    asm("{ .reg .u64 t; cvta.to.shared.u64 t, %1; cvt.u32.u64 %0, t; }"
        : "=r"(a) : "l"(p));
    return a;
}

__device__ __forceinline__ uint32_t f2tf32(float x) {
    uint32_t r;
    asm("cvt.rn.tf32.f32 %0, %1;" : "=r"(r) : "f"(x));
    return r;
}

__device__ __forceinline__ void ldsm4(uint32_t* r, uint32_t addr) {
    asm volatile("ldmatrix.sync.aligned.m8n8.x4.shared.b16 {%0,%1,%2,%3}, [%4];"
                 : "=r"(r[0]), "=r"(r[1]), "=r"(r[2]), "=r"(r[3]) : "r"(addr));
}

__device__ __forceinline__ void mma_tf32(float* c, const uint32_t* a,
                                         uint32_t b0, uint32_t b1) {
    asm volatile(
        "mma.sync.aligned.m16n8k8.row.col.f32.tf32.tf32.f32 "
        "{%0,%1,%2,%3}, {%4,%5,%6,%7}, {%8,%9}, {%0,%1,%2,%3};"
        : "+f"(c[0]), "+f"(c[1]), "+f"(c[2]), "+f"(c[3])
        : "r"(a[0]), "r"(a[1]), "r"(a[2]), "r"(a[3]), "r"(b0), "r"(b1));
}

// ===========================================================================
// mma.sync tf32 GEMM: C[M,N] = A[M,K] * B[N,K]^T  (row-major, K contiguous)
// CTA tile 128x128, K-chunk 32 (8 quads of 16B/row), 256 threads.
// Warp grid 4(m) x 2(n): warp tile 32x64 = 2 m-frags x 8 n-frags.
// Smem: A 16KB + B 16KB per buffer, double buffered = 64KB.
// Swizzle: quad index kq ^ (m & 7) -> conflict-free STS.128 and ldmatrix.
// ===========================================================================
#define GEMM_SMEM (4 * 16384)
#define BUF_STRIDE 32768

__global__ __launch_bounds__(256)
void gemm_mma(const float* __restrict__ A, const float* __restrict__ B,
              float* __restrict__ C, int M, int N, int K) {
    extern __shared__ unsigned char dsm[];
    const uint32_t sbase = smem_u32(dsm);

    const int tid  = threadIdx.x;
    const int lane = tid & 31;
    const int wid  = tid >> 5;
    const int wm   = wid & 3;     // m band (32 rows)
    const int wn   = wid >> 2;    // n band (64 cols)
    const int bm   = blockIdx.y * 128;
    const int bn   = blockIdx.x * 128;

    // Global staging: thread -> (row lrow + it*32, quad lq)
    const int lrow = tid >> 3;    // 0..31
    const int lq   = tid & 7;     // 0..7
    const float* Ag = A + (size_t)(bm + lrow) * K + lq * 4;
    const float* Bg = B + (size_t)(bn + lrow) * K + lq * 4;
    const uint32_t sq = (uint32_t)((lq ^ (lrow & 7)) * 16);
    const uint32_t stsA = sbase + (uint32_t)lrow * 128 + sq;
    const uint32_t stsB = stsA + 16384;

    // ldmatrix per-lane source rows
    const int tA = lane >> 3;
    const int mA = wm * 32 + ((tA & 1) << 3) + (lane & 7);     // +16*t
    const uint32_t kqA = (uint32_t)(tA >> 1);                  // +2*c
    const int nB = wn * 64 + ((lane >> 4) << 3) + (lane & 7);  // +16*p
    const uint32_t kqB = (uint32_t)((lane >> 3) & 1);          // +2*c
    const uint32_t swm = (uint32_t)(lane & 7);

    float cacc[2][8][4];
#pragma unroll
    for (int t = 0; t < 2; t++)
#pragma unroll
        for (int n = 0; n < 8; n++)
#pragma unroll
            for (int j = 0; j < 4; j++) cacc[t][n][j] = 0.0f;

    const int NC = K >> 5;
    float4 stA[4], stB[4];

    // Prologue: chunk 0 -> buffer 0
#pragma unroll
    for (int it = 0; it < 4; it++) {
        stA[it] = *(const float4*)(Ag + (size_t)it * 32 * K);
        stB[it] = *(const float4*)(Bg + (size_t)it * 32 * K);
    }
#pragma unroll
    for (int it = 0; it < 4; it++) {
        uint4 va = make_uint4(f2tf32(stA[it].x), f2tf32(stA[it].y),
                              f2tf32(stA[it].z), f2tf32(stA[it].w));
        uint4 vb = make_uint4(f2tf32(stB[it].x), f2tf32(stB[it].y),
                              f2tf32(stB[it].z), f2tf32(stB[it].w));
        asm volatile("st.shared.v4.b32 [%0], {%1,%2,%3,%4};" ::
                     "r"(stsA + it * 32 * 128u), "r"(va.x), "r"(va.y), "r"(va.z), "r"(va.w));
        asm volatile("st.shared.v4.b32 [%0], {%1,%2,%3,%4};" ::
                     "r"(stsB + it * 32 * 128u), "r"(vb.x), "r"(vb.y), "r"(vb.z), "r"(vb.w));
    }
    __syncthreads();

    for (int ch = 0; ch < NC; ch++) {
        const uint32_t buf = (uint32_t)(ch & 1) * BUF_STRIDE;
        if (ch + 1 < NC) {
            const float* Agn = Ag + (ch + 1) * 32;
            const float* Bgn = Bg + (ch + 1) * 32;
#pragma unroll
            for (int it = 0; it < 4; it++) {
                stA[it] = *(const float4*)(Agn + (size_t)it * 32 * K);
                stB[it] = *(const float4*)(Bgn + (size_t)it * 32 * K);
            }
        }

        const uint32_t aBase = sbase + buf;
        const uint32_t bBase = sbase + buf + 16384;
#pragma unroll
        for (int c = 0; c < 4; c++) {
            uint32_t afr[2][4];
#pragma unroll
            for (int t = 0; t < 2; t++) {
                uint32_t q = (2u * c + kqA) ^ swm;
                ldsm4(afr[t], aBase + (uint32_t)(mA + 16 * t) * 128 + q * 16);
            }
            uint32_t bfr[4][4];
#pragma unroll
            for (int p = 0; p < 4; p++) {
                uint32_t q = (2u * c + kqB) ^ swm;
                ldsm4(bfr[p], bBase + (uint32_t)(nB + 16 * p) * 128 + q * 16);
            }
#pragma unroll
            for (int t = 0; t < 2; t++)
#pragma unroll
                for (int p = 0; p < 4; p++) {
                    mma_tf32(cacc[t][2 * p],     afr[t], bfr[p][0], bfr[p][1]);
                    mma_tf32(cacc[t][2 * p + 1], afr[t], bfr[p][2], bfr[p][3]);
                }
        }
        __syncthreads();

        if (ch + 1 < NC) {
            const uint32_t nbuf = (uint32_t)((ch + 1) & 1) * BUF_STRIDE;
#pragma unroll
            for (int it = 0; it < 4; it++) {
                uint4 va = make_uint4(f2tf32(stA[it].x), f2tf32(stA[it].y),
                                      f2tf32(stA[it].z), f2tf32(stA[it].w));
                uint4 vb = make_uint4(f2tf32(stB[it].x), f2tf32(stB[it].y),
                                      f2tf32(stB[it].z), f2tf32(stB[it].w));
                asm volatile("st.shared.v4.b32 [%0], {%1,%2,%3,%4};" ::
                             "r"(stsA + nbuf + it * 32 * 128u),
                             "r"(va.x), "r"(va.y), "r"(va.z), "r"(va.w));
                asm volatile("st.shared.v4.b32 [%0], {%1,%2,%3,%4};" ::
                             "r"(stsB + nbuf + it * 32 * 128u),
                             "r"(vb.x), "r"(vb.y), "r"(vb.z), "r"(vb.w));
            }
            __syncthreads();
        }
    }

    // Epilogue: c0=(g,2w) c1=(g,2w+1) c2=(g+8,2w) c3=(g+8,2w+1)
    const int g = lane >> 2;
    const int w2 = (lane & 3) * 2;
#pragma unroll
    for (int t = 0; t < 2; t++) {
        const int row0 = bm + wm * 32 + t * 16 + g;
        const int col0 = bn + wn * 64 + w2;
#pragma unroll
        for (int n = 0; n < 8; n++) {
            float* p0 = C + (size_t)row0 * N + col0 + n * 8;
            float* p1 = C + (size_t)(row0 + 8) * N + col0 + n * 8;
            *(float2*)p0 = make_float2(cacc[t][n][0], cacc[t][n][1]);
            *(float2*)p1 = make_float2(cacc[t][n][2], cacc[t][n][3]);
        }
    }
}

// ---------------------------------------------------------------------------
// Flash attention, causal, fp32 (unchanged from R1 — proven correct).
// ---------------------------------------------------------------------------
#define BM 64
#define BN 64
#define FA_SMEM ((3 * BM * DHEAD + BM * BN) * (int)sizeof(float))

__global__ __launch_bounds__(256, 1)
void flash_attn(const float* __restrict__ qkv, float* __restrict__ out) {
    extern __shared__ float sm[];
    float* Qs = sm;
    float* Ks = Qs + BM * DHEAD;
    float* Vs = Ks + BN * DHEAD;
    float* Ps = Vs + BN * DHEAD;

    const int tid = threadIdx.x;
    const int bh = blockIdx.y;
    const int b = bh >> 4;
    const int h = bh & 15;
    const int q0 = blockIdx.x * BM;

    const float scale = 0.08838834764831845f;
    const size_t base = (size_t)b * S_LEN * E3 + (size_t)h * 384;

#pragma unroll
    for (int it = 0; it < (BM * DHEAD / 4) / 256; it++) {
        int i = tid + it * 256;
        int r = i >> 5, c4 = (i & 31) << 2;
        float4 v = *(const float4*)(qkv + base + (size_t)(q0 + r) * E3 + c4);
        v.x *= scale; v.y *= scale; v.z *= scale; v.w *= scale;
        *(float4*)(Qs + r * DHEAD + c4) = v;
    }

    const int ty = tid >> 4;
    const int tx = tid & 15;

    float o[4][8];
    float m_i[4], l_i[4];
#pragma unroll
    for (int i = 0; i < 4; i++) {
        m_i[i] = -1e30f; l_i[i] = 0.0f;
#pragma unroll
        for (int j = 0; j < 8; j++) o[i][j] = 0.0f;
    }

    const int nkt = q0 / BN + 1;
    for (int kb = 0; kb < nkt; kb++) {
        const int k0 = kb * BN;
        __syncthreads();
#pragma unroll
        for (int it = 0; it < (BN * DHEAD / 4) / 256; it++) {
            int i = tid + it * 256;
            int r = i >> 5, c4 = (i & 31) << 2;
            const float* p = qkv + base + (size_t)(k0 + r) * E3 + c4;
            *(float4*)(Ks + r * DHEAD + c4) = *(const float4*)(p + 128);
            *(float4*)(Vs + r * DHEAD + c4) = *(const float4*)(p + 256);
        }
        __syncthreads();

        float s[4][4];
#pragma unroll
        for (int i = 0; i < 4; i++)
#pragma unroll
            for (int j = 0; j < 4; j++) s[i][j] = 0.0f;

#pragma unroll 4
        for (int kk = 0; kk < DHEAD; kk += 4) {
            float4 qv[4], kv[4];
#pragma unroll
            for (int i = 0; i < 4; i++)
                qv[i] = *(const float4*)(Qs + (ty * 4 + i) * DHEAD + kk);
#pragma unroll
            for (int j = 0; j < 4; j++)
                kv[j] = *(const float4*)(Ks + (tx * 4 + j) * DHEAD + kk);
#pragma unroll
            for (int i = 0; i < 4; i++)
#pragma unroll
                for (int j = 0; j < 4; j++) {
                    s[i][j] = fmaf(qv[i].x, kv[j].x, s[i][j]);
                    s[i][j] = fmaf(qv[i].y, kv[j].y, s[i][j]);
                    s[i][j] = fmaf(qv[i].z, kv[j].z, s[i][j]);
                    s[i][j] = fmaf(qv[i].w, kv[j].w, s[i][j]);
                }
        }

        if (kb == nkt - 1) {
#pragma unroll
            for (int i = 0; i < 4; i++)
#pragma unroll
                for (int j = 0; j < 4; j++)
                    if (tx * 4 + j > ty * 4 + i) s[i][j] = -1e30f;
        }

#pragma unroll
        for (int i = 0; i < 4; i++) {
            float mx = fmaxf(fmaxf(s[i][0], s[i][1]), fmaxf(s[i][2], s[i][3]));
#pragma unroll
            for (int off = 1; off < 16; off <<= 1)
                mx = fmaxf(mx, __shfl_xor_sync(0xffffffffu, mx, off));
            float m_new = fmaxf(m_i[i], mx);
            float corr = __expf(m_i[i] - m_new);
            float rs = 0.0f;
#pragma unroll
            for (int j = 0; j < 4; j++) {
                float p = __expf(s[i][j] - m_new);
                s[i][j] = p;
                rs += p;
            }
#pragma unroll
            for (int off = 1; off < 16; off <<= 1)
                rs += __shfl_xor_sync(0xffffffffu, rs, off);
            l_i[i] = l_i[i] * corr + rs;
            m_i[i] = m_new;
#pragma unroll
            for (int j = 0; j < 8; j++) o[i][j] *= corr;
        }

#pragma unroll
        for (int i = 0; i < 4; i++)
#pragma unroll
            for (int j = 0; j < 4; j++)
                Ps[(ty * 4 + i) * BN + tx * 4 + j] = s[i][j];
        __syncthreads();

#pragma unroll 4
        for (int kk = 0; kk < BN; kk++) {
            float pr[4];
#pragma unroll
            for (int i = 0; i < 4; i++) pr[i] = Ps[(ty * 4 + i) * BN + kk];
            float4 v0 = *(const float4*)(Vs + kk * DHEAD + tx * 8);
            float4 v1 = *(const float4*)(Vs + kk * DHEAD + tx * 8 + 4);
#pragma unroll
            for (int i = 0; i < 4; i++) {
                o[i][0] = fmaf(pr[i], v0.x, o[i][0]);
                o[i][1] = fmaf(pr[i], v0.y, o[i][1]);
                o[i][2] = fmaf(pr[i], v0.z, o[i][2]);
                o[i][3] = fmaf(pr[i], v0.w, o[i][3]);
                o[i][4] = fmaf(pr[i], v1.x, o[i][4]);
                o[i][5] = fmaf(pr[i], v1.y, o[i][5]);
                o[i][6] = fmaf(pr[i], v1.z, o[i][6]);
                o[i][7] = fmaf(pr[i], v1.w, o[i][7]);
            }
        }
    }

#pragma unroll
    for (int i = 0; i < 4; i++) {
        float inv = 1.0f / l_i[i];
        float* orow = out + (size_t)((size_t)b * S_LEN + q0 + ty * 4 + i) * D_MODEL
                          + h * DHEAD + tx * 8;
        float4 v0 = make_float4(o[i][0]*inv, o[i][1]*inv, o[i][2]*inv, o[i][3]*inv);
        float4 v1 = make_float4(o[i][4]*inv, o[i][5]*inv, o[i][6]*inv, o[i][7]*inv);
        *(float4*)(orow)     = v0;
        *(float4*)(orow + 4) = v1;
    }
}

// ---------------------------------------------------------------------------
extern "C" void kernel_launch(void* const* d_in, const int* in_sizes, int n_in,
                              void* d_out, int out_size) {
    const float* x     = (const float*)d_in[0];  // [B,S,D]
    const float* w_in  = (const float*)d_in[1];  // [3*H*DH, D]
    const float* w_out = (const float*)d_in[2];  // [D, H*DH]
    float* out = (float*)d_out;                  // [B,S,D]

    float *qkv, *attn;
    cudaGetSymbolAddress((void**)&qkv, g_qkv);
    cudaGetSymbolAddress((void**)&attn, g_attn);

    cudaFuncSetAttribute(gemm_mma, cudaFuncAttributeMaxDynamicSharedMemorySize,
                         GEMM_SMEM);
    cudaFuncSetAttribute(flash_attn, cudaFuncAttributeMaxDynamicSharedMemorySize,
                         FA_SMEM);

    // 1) QKV projection: [4096,2048] x [6144,2048]^T -> [4096,6144]
    dim3 g1(E3 / 128, M_TOK / 128);
    gemm_mma<<<g1, 256, GEMM_SMEM>>>(x, w_in, qkv, M_TOK, E3, D_MODEL);

    // 2) Causal flash attention -> [4096, 2048]
    dim3 g2(S_LEN / BM, BATCH * NH);
    flash_attn<<<g2, 256, FA_SMEM>>>(qkv, attn);

    // 3) Output projection: [4096,2048] x [2048,2048]^T -> [4096,2048]
    dim3 g3(D_MODEL / 128, M_TOK / 128);
    gemm_mma<<<g3, 256, GEMM_SMEM>>>(attn, w_out, out, M_TOK, D_MODEL, D_MODEL);
}

// round 4
// speedup vs baseline: 4.7510x; 2.9349x over previous
#include <cuda_runtime.h>
#include <cstdint>

// Problem constants
#define BATCH   2
#define S_LEN   2048
#define D_MODEL 2048
#define NH      16
#define DHEAD   128
#define M_TOK   (BATCH * S_LEN)     // 4096 tokens
#define E3      (3 * NH * DHEAD)    // 6144 qkv features

// Scratch (alloc-free rule: __device__ globals)
__device__ float g_qkv[(size_t)M_TOK * E3];           // [4096, 6144]
__device__ float g_attn[(size_t)M_TOK * D_MODEL];     // [4096, 2048]
__device__ float g_vt[(size_t)BATCH * NH * DHEAD * S_LEN]; // [b,h,dh,s] 32MB

// ===========================================================================
// PTX helpers (generic sm_80+ only — toolchain targets plain compute_103)
// ===========================================================================
__device__ __forceinline__ uint32_t smem_u32(const void* p) {
    uint32_t a;
    asm("{ .reg .u64 t; cvta.to.shared.u64 t, %1; cvt.u32.u64 %0, t; }"
        : "=r"(a) : "l"(p));
    return a;
}

__device__ __forceinline__ uint32_t f2tf32(float x) {
    uint32_t r;
    asm("cvt.rn.tf32.f32 %0, %1;" : "=r"(r) : "f"(x));
    return r;
}

__device__ __forceinline__ void ldsm4(uint32_t* r, uint32_t addr) {
    asm volatile("ldmatrix.sync.aligned.m8n8.x4.shared.b16 {%0,%1,%2,%3}, [%4];"
                 : "=r"(r[0]), "=r"(r[1]), "=r"(r[2]), "=r"(r[3]) : "r"(addr));
}

__device__ __forceinline__ void mma_tf32(float* c, const uint32_t* a,
                                         uint32_t b0, uint32_t b1) {
    asm volatile(
        "mma.sync.aligned.m16n8k8.row.col.f32.tf32.tf32.f32 "
        "{%0,%1,%2,%3}, {%4,%5,%6,%7}, {%8,%9}, {%0,%1,%2,%3};"
        : "+f"(c[0]), "+f"(c[1]), "+f"(c[2]), "+f"(c[3])
        : "r"(a[0]), "r"(a[1]), "r"(a[2]), "r"(a[3]), "r"(b0), "r"(b1));
}

__device__ __forceinline__ void sts128(uint32_t addr, uint32_t x, uint32_t y,
                                       uint32_t z, uint32_t w) {
    asm volatile("st.shared.v4.b32 [%0], {%1,%2,%3,%4};"
                 :: "r"(addr), "r"(x), "r"(y), "r"(z), "r"(w));
}

__device__ __forceinline__ void sts64(uint32_t addr, uint32_t x, uint32_t y) {
    asm volatile("st.shared.v2.b32 [%0], {%1,%2};" :: "r"(addr), "r"(x), "r"(y));
}

// ===========================================================================
// mma.sync tf32 GEMM: C[M,N] = A[M,K] * B[N,K]^T (unchanged from R3 — WIN)
// ===========================================================================
#define GEMM_SMEM (4 * 16384)
#define BUF_STRIDE 32768

__global__ __launch_bounds__(256)
void gemm_mma(const float* __restrict__ A, const float* __restrict__ B,
              float* __restrict__ C, int M, int N, int K) {
    extern __shared__ unsigned char dsm[];
    const uint32_t sbase = smem_u32(dsm);

    const int tid  = threadIdx.x;
    const int lane = tid & 31;
    const int wid  = tid >> 5;
    const int wm   = wid & 3;
    const int wn   = wid >> 2;
    const int bm   = blockIdx.y * 128;
    const int bn   = blockIdx.x * 128;

    const int lrow = tid >> 3;
    const int lq   = tid & 7;
    const float* Ag = A + (size_t)(bm + lrow) * K + lq * 4;
    const float* Bg = B + (size_t)(bn + lrow) * K + lq * 4;
    const uint32_t sq = (uint32_t)((lq ^ (lrow & 7)) * 16);
    const uint32_t stsA = sbase + (uint32_t)lrow * 128 + sq;
    const uint32_t stsB = stsA + 16384;

    const int tA = lane >> 3;
    const int mA = wm * 32 + ((tA & 1) << 3) + (lane & 7);
    const uint32_t kqA = (uint32_t)(tA >> 1);
    const int nB = wn * 64 + ((lane >> 4) << 3) + (lane & 7);
    const uint32_t kqB = (uint32_t)((lane >> 3) & 1);
    const uint32_t swm = (uint32_t)(lane & 7);

    float cacc[2][8][4];
#pragma unroll
    for (int t = 0; t < 2; t++)
#pragma unroll
        for (int n = 0; n < 8; n++)
#pragma unroll
            for (int j = 0; j < 4; j++) cacc[t][n][j] = 0.0f;

    const int NC = K >> 5;
    float4 stA[4], stB[4];

#pragma unroll
    for (int it = 0; it < 4; it++) {
        stA[it] = *(const float4*)(Ag + (size_t)it * 32 * K);
        stB[it] = *(const float4*)(Bg + (size_t)it * 32 * K);
    }
#pragma unroll
    for (int it = 0; it < 4; it++) {
        sts128(stsA + it * 32 * 128u, f2tf32(stA[it].x), f2tf32(stA[it].y),
               f2tf32(stA[it].z), f2tf32(stA[it].w));
        sts128(stsB + it * 32 * 128u, f2tf32(stB[it].x), f2tf32(stB[it].y),
               f2tf32(stB[it].z), f2tf32(stB[it].w));
    }
    __syncthreads();

    for (int ch = 0; ch < NC; ch++) {
        const uint32_t buf = (uint32_t)(ch & 1) * BUF_STRIDE;
        if (ch + 1 < NC) {
            const float* Agn = Ag + (ch + 1) * 32;
            const float* Bgn = Bg + (ch + 1) * 32;
#pragma unroll
            for (int it = 0; it < 4; it++) {
                stA[it] = *(const float4*)(Agn + (size_t)it * 32 * K);
                stB[it] = *(const float4*)(Bgn + (size_t)it * 32 * K);
            }
        }

        const uint32_t aBase = sbase + buf;
        const uint32_t bBase = sbase + buf + 16384;
#pragma unroll
        for (int c = 0; c < 4; c++) {
            uint32_t afr[2][4];
#pragma unroll
            for (int t = 0; t < 2; t++) {
                uint32_t q = (2u * c + kqA) ^ swm;
                ldsm4(afr[t], aBase + (uint32_t)(mA + 16 * t) * 128 + q * 16);
            }
            uint32_t bfr[4][4];
#pragma unroll
            for (int p = 0; p < 4; p++) {
                uint32_t q = (2u * c + kqB) ^ swm;
                ldsm4(bfr[p], bBase + (uint32_t)(nB + 16 * p) * 128 + q * 16);
            }
#pragma unroll
            for (int t = 0; t < 2; t++)
#pragma unroll
                for (int p = 0; p < 4; p++) {
                    mma_tf32(cacc[t][2 * p],     afr[t], bfr[p][0], bfr[p][1]);
                    mma_tf32(cacc[t][2 * p + 1], afr[t], bfr[p][2], bfr[p][3]);
                }
        }
        __syncthreads();

        if (ch + 1 < NC) {
            const uint32_t nbuf = (uint32_t)((ch + 1) & 1) * BUF_STRIDE;
#pragma unroll
            for (int it = 0; it < 4; it++) {
                sts128(stsA + nbuf + it * 32 * 128u, f2tf32(stA[it].x),
                       f2tf32(stA[it].y), f2tf32(stA[it].z), f2tf32(stA[it].w));
                sts128(stsB + nbuf + it * 32 * 128u, f2tf32(stB[it].x),
                       f2tf32(stB[it].y), f2tf32(stB[it].z), f2tf32(stB[it].w));
            }
            __syncthreads();
        }
    }

    const int g = lane >> 2;
    const int w2 = (lane & 3) * 2;
#pragma unroll
    for (int t = 0; t < 2; t++) {
        const int row0 = bm + wm * 32 + t * 16 + g;
        const int col0 = bn + wn * 64 + w2;
#pragma unroll
        for (int n = 0; n < 8; n++) {
            float* p0 = C + (size_t)row0 * N + col0 + n * 8;
            float* p1 = C + (size_t)(row0 + 8) * N + col0 + n * 8;
            *(float2*)p0 = make_float2(cacc[t][n][0], cacc[t][n][1]);
            *(float2*)p1 = make_float2(cacc[t][n][2], cacc[t][n][3]);
        }
    }
}

// ===========================================================================
// V transpose pre-pass: g_qkv V-slices -> g_vt[b,h,dh,s], tf32-rounded.
// Tiled 32x32 via smem; both sides coalesced.
// ===========================================================================
__global__ __launch_bounds__(256)
void transpose_v(const float* __restrict__ qkv, float* __restrict__ vt) {
    __shared__ float t[32][33];
    const int bh = blockIdx.z;
    const int b = bh >> 4, h = bh & 15;
    const int s0 = blockIdx.x * 32;
    const int d0 = blockIdx.y * 32;
    const int tx = threadIdx.x & 31;
    const int ty = threadIdx.x >> 5;

    const float* src = qkv + (size_t)b * S_LEN * E3 + (size_t)h * 384 + 256;
#pragma unroll
    for (int i = ty; i < 32; i += 8)
        t[i][tx] = src[(size_t)(s0 + i) * E3 + d0 + tx];
    __syncthreads();
    float* dst = vt + ((size_t)bh * DHEAD + d0) * S_LEN + s0;
#pragma unroll
    for (int i = ty; i < 32; i += 8)
        dst[(size_t)i * S_LEN + tx] = __uint_as_float(f2tf32(t[tx][i]));
}

// ===========================================================================
// Flash attention on mma.sync tf32. Causal.
// CTA: 128 q-rows of one (b,h); 8 warps, warp w owns m16 band rows [16w,16w+16).
// kv tiles of 64. Smem (bytes):
//   Qs  128 rows x 512B (quad-xor swizzle)      @ 0       (65536)
//   Ks   64 rows x 512B (quad-xor swizzle)      @ 65536   (32768)
//   Vt  2 x [128 dh-rows x 272B] (key-contig)   @ 98304   (69632)
//   Ps  128 rows x 272B                         @ 167936  (34816)
// ===========================================================================
#define FBM 128
#define FBN 64
#define OFF_Q 0
#define OFF_K 65536
#define OFF_V 98304
#define VT_SZ 34816
#define OFF_P 167936
#define FA_SMEM (OFF_P + VT_SZ)   // 202752

__global__ __launch_bounds__(256, 1)
void flash_attn_mma(const float* __restrict__ qkv, const float* __restrict__ vt,
                    float* __restrict__ out) {
    extern __shared__ unsigned char fsm[];
    const uint32_t sb = smem_u32(fsm);
    const int tid = threadIdx.x;
    const int lane = tid & 31;
    const int w = tid >> 5;
    const int bh = blockIdx.y;
    const int b = bh >> 4, h = bh & 15;
    const int q0 = blockIdx.x * FBM;

    const float scale = 0.08838834764831845f;  // 1/sqrt(128)
    const size_t qbase = (size_t)b * S_LEN * E3 + (size_t)h * 384;

    // Load Q tile (scaled, tf32) : 128 rows x 128 cols
#pragma unroll
    for (int it = 0; it < 16; it++) {
        int idx = tid + it * 256;
        int r = idx >> 5, lq = idx & 31;
        float4 v = *(const float4*)(qkv + qbase + (size_t)(q0 + r) * E3 + lq * 4);
        uint32_t o = sb + OFF_Q + (uint32_t)r * 512 + (uint32_t)((lq ^ (r & 7)) * 16);
        sts128(o, f2tf32(v.x * scale), f2tf32(v.y * scale),
                  f2tf32(v.z * scale), f2tf32(v.w * scale));
    }

    // ldmatrix per-lane indices
    const int tA = lane >> 3;
    const int rA = ((tA & 1) << 3) + (lane & 7);     // row within m16 band
    const uint32_t kqA = (uint32_t)(tA >> 1);
    const int rB = ((lane >> 4) << 3) + (lane & 7);  // row within n16 pair
    const uint32_t kqB = (uint32_t)((lane >> 3) & 1);
    const uint32_t swm = (uint32_t)(lane & 7);
    const int g = lane >> 2;
    const int qw = lane & 3;

    float o_acc[16][4];
#pragma unroll
    for (int n = 0; n < 16; n++)
#pragma unroll
        for (int j = 0; j < 4; j++) o_acc[n][j] = 0.0f;
    float mr0 = -1e30f, mr1 = -1e30f, lr0 = 0.0f, lr1 = 0.0f;

    const int row0g = q0 + w * 16 + g;   // global q row for c0/c1
    const int row1g = row0g + 8;         // global q row for c2/c3

    const int nkt = q0 / FBN + 2;
    for (int kb = 0; kb < nkt; kb++) {
        const int k0 = kb * FBN;
        const uint32_t vbuf = sb + OFF_V + (uint32_t)(kb & 1) * VT_SZ;

        // Load K tile (64 x 128, tf32, swizzled)
#pragma unroll
        for (int it = 0; it < 8; it++) {
            int idx = tid + it * 256;
            int r = idx >> 5, lq = idx & 31;
            float4 v = *(const float4*)(qkv + qbase + (size_t)(k0 + r) * E3 + 128 + lq * 4);
            uint32_t o = sb + OFF_K + (uint32_t)r * 512 + (uint32_t)((lq ^ (r & 7)) * 16);
            sts128(o, f2tf32(v.x), f2tf32(v.y), f2tf32(v.z), f2tf32(v.w));
        }
        // Load Vt tile (128 dh-rows x 64 keys; already tf32)
        const float* vsrc = vt + (size_t)bh * DHEAD * S_LEN + k0;
#pragma unroll
        for (int it = 0; it < 8; it++) {
            int idx = tid + it * 256;
            int dh = idx >> 4, kq = idx & 15;
            float4 v = *(const float4*)(vsrc + (size_t)dh * S_LEN + kq * 4);
            sts128(vbuf + (uint32_t)dh * 272 + (uint32_t)kq * 16,
                   __float_as_uint(v.x), __float_as_uint(v.y),
                   __float_as_uint(v.z), __float_as_uint(v.w));
        }
        __syncthreads();

        const bool active = (k0 <= q0 + w * 16 + 15);
        if (active) {
            // S = Q * K^T : m16 x n64 x k128
            float sf[8][4];
#pragma unroll
            for (int n = 0; n < 8; n++)
#pragma unroll
                for (int j = 0; j < 4; j++) sf[n][j] = 0.0f;

#pragma unroll
            for (int c = 0; c < 16; c++) {
                uint32_t af[4];
                uint32_t qa = (2u * c + kqA) ^ swm;
                ldsm4(af, sb + OFF_Q + (uint32_t)(w * 16 + rA) * 512 + qa * 16);
#pragma unroll
                for (int p = 0; p < 4; p++) {
                    uint32_t bf[4];
                    uint32_t qb = (2u * c + kqB) ^ swm;
                    ldsm4(bf, sb + OFF_K + (uint32_t)(p * 16 + rB) * 512 + qb * 16);
                    mma_tf32(sf[2 * p],     af, bf[0], bf[1]);
                    mma_tf32(sf[2 * p + 1], af, bf[2], bf[3]);
                }
            }

            // Causal mask (only tiles crossing the diagonal of this warp band)
            if (k0 + FBN - 1 > q0 + w * 16) {
#pragma unroll
                for (int n = 0; n < 8; n++) {
                    int col = k0 + n * 8 + qw * 2;
                    if (col > row0g)     sf[n][0] = -1e30f;
                    if (col + 1 > row0g) sf[n][1] = -1e30f;
                    if (col > row1g)     sf[n][2] = -1e30f;
                    if (col + 1 > row1g) sf[n][3] = -1e30f;
                }
            }

            // Online softmax (rows g and g+8 of the warp band)
            float mx0 = -1e30f, mx1 = -1e30f;
#pragma unroll
            for (int n = 0; n < 8; n++) {
                mx0 = fmaxf(mx0, fmaxf(sf[n][0], sf[n][1]));
                mx1 = fmaxf(mx1, fmaxf(sf[n][2], sf[n][3]));
            }
            mx0 = fmaxf(mx0, __shfl_xor_sync(0xffffffffu, mx0, 1));
            mx0 = fmaxf(mx0, __shfl_xor_sync(0xffffffffu, mx0, 2));
            mx1 = fmaxf(mx1, __shfl_xor_sync(0xffffffffu, mx1, 1));
            mx1 = fmaxf(mx1, __shfl_xor_sync(0xffffffffu, mx1, 2));
            const float mn0 = fmaxf(mr0, mx0);
            const float mn1 = fmaxf(mr1, mx1);
            const float cor0 = __expf(mr0 - mn0);
            const float cor1 = __expf(mr1 - mn1);
            float rs0 = 0.0f, rs1 = 0.0f;
#pragma unroll
            for (int n = 0; n < 8; n++) {
                sf[n][0] = __expf(sf[n][0] - mn0);
                sf[n][1] = __expf(sf[n][1] - mn0);
                sf[n][2] = __expf(sf[n][2] - mn1);
                sf[n][3] = __expf(sf[n][3] - mn1);
                rs0 += sf[n][0] + sf[n][1];
                rs1 += sf[n][2] + sf[n][3];
            }
            rs0 += __shfl_xor_sync(0xffffffffu, rs0, 1);
            rs0 += __shfl_xor_sync(0xffffffffu, rs0, 2);
            rs1 += __shfl_xor_sync(0xffffffffu, rs1, 1);
            rs1 += __shfl_xor_sync(0xffffffffu, rs1, 2);
            lr0 = lr0 * cor0 + rs0;  mr0 = mn0;
            lr1 = lr1 * cor1 + rs1;  mr1 = mn1;
#pragma unroll
            for (int n = 0; n < 16; n++) {
                o_acc[n][0] *= cor0; o_acc[n][1] *= cor0;
                o_acc[n][2] *= cor1; o_acc[n][3] *= cor1;
            }

            // Write P (tf32) to Ps: rows (16w+g) and (16w+g+8)
            const uint32_t pr0 = sb + OFF_P + (uint32_t)(w * 16 + g) * 272
                               + (uint32_t)qw * 8;
#pragma unroll
            for (int n = 0; n < 8; n++) {
                sts64(pr0 + (uint32_t)n * 32, f2tf32(sf[n][0]), f2tf32(sf[n][1]));
                sts64(pr0 + 8 * 272 + (uint32_t)n * 32,
                      f2tf32(sf[n][2]), f2tf32(sf[n][3]));
            }
        }
        __syncthreads();

        if (active) {
            // O += P * Vt^T : m16 x n128 x k64
#pragma unroll
            for (int c = 0; c < 8; c++) {
                uint32_t af[4];
                ldsm4(af, sb + OFF_P + (uint32_t)(w * 16 + rA) * 272
                          + (2u * c + kqA) * 16);
#pragma unroll
                for (int p = 0; p < 8; p++) {
                    uint32_t bf[4];
                    ldsm4(bf, vbuf + (uint32_t)(p * 16 + rB) * 272
                              + (2u * c + kqB) * 16);
                    mma_tf32(o_acc[2 * p],     af, bf[0], bf[1]);
                    mma_tf32(o_acc[2 * p + 1], af, bf[2], bf[3]);
                }
            }
        }
    }

    // Epilogue: normalize rows and write [token, h*128+col]
    const float inv0 = 1.0f / lr0;
    const float inv1 = 1.0f / lr1;
#pragma unroll
    for (int n = 0; n < 16; n++) {
        const int col = h * DHEAD + n * 8 + qw * 2;
        float* p0 = out + (size_t)((size_t)b * S_LEN + row0g) * D_MODEL + col;
        float* p1 = out + (size_t)((size_t)b * S_LEN + row1g) * D_MODEL + col;
        *(float2*)p0 = make_float2(o_acc[n][0] * inv0, o_acc[n][1] * inv0);
        *(float2*)p1 = make_float2(o_acc[n][2] * inv1, o_acc[n][3] * inv1);
    }
}

// ---------------------------------------------------------------------------
extern "C" void kernel_launch(void* const* d_in, const int* in_sizes, int n_in,
                              void* d_out, int out_size) {
    const float* x     = (const float*)d_in[0];  // [B,S,D]
    const float* w_in  = (const float*)d_in[1];  // [3*H*DH, D]
    const float* w_out = (const float*)d_in[2];  // [D, H*DH]
    float* out = (float*)d_out;                  // [B,S,D]

    float *qkv, *attn, *vt;
    cudaGetSymbolAddress((void**)&qkv, g_qkv);
    cudaGetSymbolAddress((void**)&attn, g_attn);
    cudaGetSymbolAddress((void**)&vt, g_vt);

    cudaFuncSetAttribute(gemm_mma, cudaFuncAttributeMaxDynamicSharedMemorySize,
                         GEMM_SMEM);
    cudaFuncSetAttribute(flash_attn_mma, cudaFuncAttributeMaxDynamicSharedMemorySize,
                         FA_SMEM);

    // 1) QKV projection: [4096,2048] x [6144,2048]^T -> [4096,6144]
    dim3 g1(E3 / 128, M_TOK / 128);
    gemm_mma<<<g1, 256, GEMM_SMEM>>>(x, w_in, qkv, M_TOK, E3, D_MODEL);

    // 2) V transpose pre-pass -> g_vt[b,h,dh,s]
    dim3 gt(S_LEN / 32, DHEAD / 32, BATCH * NH);
    transpose_v<<<gt, 256>>>(qkv, vt);

    // 3) Causal flash attention (tensor cores) -> [4096, 2048]
    dim3 g2(S_LEN / FBM, BATCH * NH);
    flash_attn_mma<<<g2, 256, FA_SMEM>>>(qkv, vt, attn);

    // 4) Output projection: [4096,2048] x [2048,2048]^T -> [4096,2048]
    dim3 g3(D_MODEL / 128, M_TOK / 128);
    gemm_mma<<<g3, 256, GEMM_SMEM>>>(attn, w_out, out, M_TOK, D_MODEL, D_MODEL);
}

// round 5
// speedup vs baseline: 6.1533x; 1.2952x over previous
#include <cuda_runtime.h>
#include <cstdint>

// Problem constants
#define BATCH   2
#define S_LEN   2048
#define D_MODEL 2048
#define NH      16
#define DHEAD   128
#define M_TOK   (BATCH * S_LEN)     // 4096 tokens
#define E3      (3 * NH * DHEAD)    // 6144 qkv features

// Scratch (alloc-free rule: __device__ globals)
__device__ float g_qkv[(size_t)M_TOK * E3];                // [4096, 6144]
__device__ float g_attn[(size_t)M_TOK * D_MODEL];          // [4096, 2048]
__device__ float g_vt[(size_t)BATCH * NH * DHEAD * S_LEN]; // [b,h,dh,s]
__device__ float g_xtf[(size_t)M_TOK * D_MODEL];           // tf32-rounded x
__device__ float g_wintf[(size_t)E3 * D_MODEL];            // tf32-rounded w_in
__device__ float g_wouttf[(size_t)D_MODEL * D_MODEL];      // tf32-rounded w_out

// ===========================================================================
// PTX helpers (generic sm_80+ only — toolchain targets plain compute_103)
// ===========================================================================
__device__ __forceinline__ uint32_t smem_u32(const void* p) {
    uint32_t a;
    asm("{ .reg .u64 t; cvta.to.shared.u64 t, %1; cvt.u32.u64 %0, t; }"
        : "=r"(a) : "l"(p));
    return a;
}

__device__ __forceinline__ uint32_t f2tf32(float x) {
    uint32_t r;
    asm("cvt.rn.tf32.f32 %0, %1;" : "=r"(r) : "f"(x));
    return r;
}

__device__ __forceinline__ void ldsm4(uint32_t* r, uint32_t addr) {
    asm volatile("ldmatrix.sync.aligned.m8n8.x4.shared.b16 {%0,%1,%2,%3}, [%4];"
                 : "=r"(r[0]), "=r"(r[1]), "=r"(r[2]), "=r"(r[3]) : "r"(addr));
}

__device__ __forceinline__ void mma_tf32(float* c, const uint32_t* a,
                                         uint32_t b0, uint32_t b1) {
    asm volatile(
        "mma.sync.aligned.m16n8k8.row.col.f32.tf32.tf32.f32 "
        "{%0,%1,%2,%3}, {%4,%5,%6,%7}, {%8,%9}, {%0,%1,%2,%3};"
        : "+f"(c[0]), "+f"(c[1]), "+f"(c[2]), "+f"(c[3])
        : "r"(a[0]), "r"(a[1]), "r"(a[2]), "r"(a[3]), "r"(b0), "r"(b1));
}

__device__ __forceinline__ void sts128(uint32_t addr, uint32_t x, uint32_t y,
                                       uint32_t z, uint32_t w) {
    asm volatile("st.shared.v4.b32 [%0], {%1,%2,%3,%4};"
                 :: "r"(addr), "r"(x), "r"(y), "r"(z), "r"(w));
}

__device__ __forceinline__ void sts64(uint32_t addr, uint32_t x, uint32_t y) {
    asm volatile("st.shared.v2.b32 [%0], {%1,%2};" :: "r"(addr), "r"(x), "r"(y));
}

__device__ __forceinline__ void cp16(uint32_t dst, const void* src) {
    asm volatile("cp.async.cg.shared.global [%0], [%1], 16;"
                 :: "r"(dst), "l"(src));
}
#define CP_COMMIT() asm volatile("cp.async.commit_group;" ::: "memory")
#define CP_WAIT1()  asm volatile("cp.async.wait_group 1;" ::: "memory")
#define CP_WAIT0()  asm volatile("cp.async.wait_group 0;" ::: "memory")

// ===========================================================================
// tf32 rounding pre-pass (elementwise, vectorized)
// ===========================================================================
__global__ __launch_bounds__(256)
void cvt_tf32(const float* __restrict__ src, float* __restrict__ dst, int n4) {
    int i = blockIdx.x * 256 + threadIdx.x;
    if (i < n4) {
        float4 v = ((const float4*)src)[i];
        ((uint4*)dst)[i] = make_uint4(f2tf32(v.x), f2tf32(v.y),
                                      f2tf32(v.z), f2tf32(v.w));
    }
}

// ===========================================================================
// cp.async 3-stage tf32 GEMM: C[M,N] = A[M,K] * B[N,K]^T
// Inputs MUST be pre-rounded to tf32 (low mantissa bits zero).
// CTA tile 128x128, K-chunk 32, 256 threads, warp grid 4(m)x2(n).
// Smem: 3 stages x (A 16KB + B 16KB) = 96KB. 2 CTAs/SM.
// ===========================================================================
#define NSTAGE 3
#define STAGE_B 32768
#define GEMM_SMEM (NSTAGE * STAGE_B)

__global__ __launch_bounds__(256, 2)
void gemm_mma(const float* __restrict__ A, const float* __restrict__ B,
              float* __restrict__ C, int M, int N, int K) {
    extern __shared__ unsigned char dsm[];
    const uint32_t sbase = smem_u32(dsm);

    const int tid  = threadIdx.x;
    const int lane = tid & 31;
    const int wid  = tid >> 5;
    const int wm   = wid & 3;
    const int wn   = wid >> 2;
    const int bm   = blockIdx.y * 128;
    const int bn   = blockIdx.x * 128;

    // cp.async staging: thread -> (row lrow + it*32, quad lq)
    const int lrow = tid >> 3;
    const int lq   = tid & 7;
    const float* Ag = A + (size_t)(bm + lrow) * K + lq * 4;
    const float* Bg = B + (size_t)(bn + lrow) * K + lq * 4;
    const uint32_t sq = (uint32_t)((lq ^ (lrow & 7)) * 16);
    const uint32_t stsA = sbase + (uint32_t)lrow * 128 + sq;
    const uint32_t stsB = stsA + 16384;

    // ldmatrix per-lane indices
    const int tA = lane >> 3;
    const int mA = wm * 32 + ((tA & 1) << 3) + (lane & 7);
    const uint32_t kqA = (uint32_t)(tA >> 1);
    const int nB = wn * 64 + ((lane >> 4) << 3) + (lane & 7);
    const uint32_t kqB = (uint32_t)((lane >> 3) & 1);
    const uint32_t swm = (uint32_t)(lane & 7);

    float cacc[2][8][4];
#pragma unroll
    for (int t = 0; t < 2; t++)
#pragma unroll
        for (int n = 0; n < 8; n++)
#pragma unroll
            for (int j = 0; j < 4; j++) cacc[t][n][j] = 0.0f;

    const int NC = K >> 5;

    // Prologue: issue loads for stages 0..NSTAGE-2
#pragma unroll
    for (int s = 0; s < NSTAGE - 1; s++) {
        const uint32_t so = (uint32_t)s * STAGE_B;
        const int k0 = s * 32;
#pragma unroll
        for (int it = 0; it < 4; it++) {
            cp16(stsA + so + it * 32 * 128u, Ag + k0 + (size_t)it * 32 * K);
            cp16(stsB + so + it * 32 * 128u, Bg + k0 + (size_t)it * 32 * K);
        }
        CP_COMMIT();
    }

    for (int ch = 0; ch < NC; ch++) {
        CP_WAIT1();
        __syncthreads();

        // Issue loads for stage ch + NSTAGE - 1 (into the buffer freed at ch-1)
        if (ch + NSTAGE - 1 < NC) {
            const uint32_t so = (uint32_t)((ch + NSTAGE - 1) % NSTAGE) * STAGE_B;
            const int k0 = (ch + NSTAGE - 1) * 32;
#pragma unroll
            for (int it = 0; it < 4; it++) {
                cp16(stsA + so + it * 32 * 128u, Ag + k0 + (size_t)it * 32 * K);
                cp16(stsB + so + it * 32 * 128u, Bg + k0 + (size_t)it * 32 * K);
            }
        }
        CP_COMMIT();   // commit even when empty to keep group counts aligned

        // Compute on stage ch % NSTAGE
        const uint32_t aBase = sbase + (uint32_t)(ch % NSTAGE) * STAGE_B;
        const uint32_t bBase = aBase + 16384;
#pragma unroll
        for (int c = 0; c < 4; c++) {
            uint32_t afr[2][4];
#pragma unroll
            for (int t = 0; t < 2; t++) {
                uint32_t q = (2u * c + kqA) ^ swm;
                ldsm4(afr[t], aBase + (uint32_t)(mA + 16 * t) * 128 + q * 16);
            }
            uint32_t bfr[4][4];
#pragma unroll
            for (int p = 0; p < 4; p++) {
                uint32_t q = (2u * c + kqB) ^ swm;
                ldsm4(bfr[p], bBase + (uint32_t)(nB + 16 * p) * 128 + q * 16);
            }
#pragma unroll
            for (int t = 0; t < 2; t++)
#pragma unroll
                for (int p = 0; p < 4; p++) {
                    mma_tf32(cacc[t][2 * p],     afr[t], bfr[p][0], bfr[p][1]);
                    mma_tf32(cacc[t][2 * p + 1], afr[t], bfr[p][2], bfr[p][3]);
                }
        }
    }
    CP_WAIT0();

    const int g = lane >> 2;
    const int w2 = (lane & 3) * 2;
#pragma unroll
    for (int t = 0; t < 2; t++) {
        const int row0 = bm + wm * 32 + t * 16 + g;
        const int col0 = bn + wn * 64 + w2;
#pragma unroll
        for (int n = 0; n < 8; n++) {
            float* p0 = C + (size_t)row0 * N + col0 + n * 8;
            float* p1 = C + (size_t)(row0 + 8) * N + col0 + n * 8;
            *(float2*)p0 = make_float2(cacc[t][n][0], cacc[t][n][1]);
            *(float2*)p1 = make_float2(cacc[t][n][2], cacc[t][n][3]);
        }
    }
}

// ===========================================================================
// V transpose pre-pass: g_qkv V-slices -> g_vt[b,h,dh,s], tf32-rounded.
// ===========================================================================
__global__ __launch_bounds__(256)
void transpose_v(const float* __restrict__ qkv, float* __restrict__ vt) {
    __shared__ float t[32][33];
    const int bh = blockIdx.z;
    const int b = bh >> 4, h = bh & 15;
    const int s0 = blockIdx.x * 32;
    const int d0 = blockIdx.y * 32;
    const int tx = threadIdx.x & 31;
    const int ty = threadIdx.x >> 5;

    const float* src = qkv + (size_t)b * S_LEN * E3 + (size_t)h * 384 + 256;
#pragma unroll
    for (int i = ty; i < 32; i += 8)
        t[i][tx] = src[(size_t)(s0 + i) * E3 + d0 + tx];
    __syncthreads();
    float* dst = vt + ((size_t)bh * DHEAD + d0) * S_LEN + s0;
#pragma unroll
    for (int i = ty; i < 32; i += 8)
        dst[(size_t)i * S_LEN + tx] = __uint_as_float(f2tf32(t[tx][i]));
}

// ===========================================================================
// Flash attention on mma.sync tf32 (unchanged from R4 except: epilogue rounds
// output to tf32 so GEMM2 can consume it without conversion).
// ===========================================================================
#define FBM 128
#define FBN 64
#define OFF_Q 0
#define OFF_K 65536
#define OFF_V 98304
#define VT_SZ 34816
#define OFF_P 167936
#define FA_SMEM (OFF_P + VT_SZ)   // 202752

__global__ __launch_bounds__(256, 1)
void flash_attn_mma(const float* __restrict__ qkv, const float* __restrict__ vt,
                    float* __restrict__ out) {
    extern __shared__ unsigned char fsm[];
    const uint32_t sb = smem_u32(fsm);
    const int tid = threadIdx.x;
    const int lane = tid & 31;
    const int w = tid >> 5;
    const int bh = blockIdx.y;
    const int b = bh >> 4, h = bh & 15;
    const int q0 = blockIdx.x * FBM;

    const float scale = 0.08838834764831845f;  // 1/sqrt(128)
    const size_t qbase = (size_t)b * S_LEN * E3 + (size_t)h * 384;

#pragma unroll
    for (int it = 0; it < 16; it++) {
        int idx = tid + it * 256;
        int r = idx >> 5, lq = idx & 31;
        float4 v = *(const float4*)(qkv + qbase + (size_t)(q0 + r) * E3 + lq * 4);
        uint32_t o = sb + OFF_Q + (uint32_t)r * 512 + (uint32_t)((lq ^ (r & 7)) * 16);
        sts128(o, f2tf32(v.x * scale), f2tf32(v.y * scale),
                  f2tf32(v.z * scale), f2tf32(v.w * scale));
    }

    const int tA = lane >> 3;
    const int rA = ((tA & 1) << 3) + (lane & 7);
    const uint32_t kqA = (uint32_t)(tA >> 1);
    const int rB = ((lane >> 4) << 3) + (lane & 7);
    const uint32_t kqB = (uint32_t)((lane >> 3) & 1);
    const uint32_t swm = (uint32_t)(lane & 7);
    const int g = lane >> 2;
    const int qw = lane & 3;

    float o_acc[16][4];
#pragma unroll
    for (int n = 0; n < 16; n++)
#pragma unroll
        for (int j = 0; j < 4; j++) o_acc[n][j] = 0.0f;
    float mr0 = -1e30f, mr1 = -1e30f, lr0 = 0.0f, lr1 = 0.0f;

    const int row0g = q0 + w * 16 + g;
    const int row1g = row0g + 8;

    const int nkt = q0 / FBN + 2;
    for (int kb = 0; kb < nkt; kb++) {
        const int k0 = kb * FBN;
        const uint32_t vbuf = sb + OFF_V + (uint32_t)(kb & 1) * VT_SZ;

#pragma unroll
        for (int it = 0; it < 8; it++) {
            int idx = tid + it * 256;
            int r = idx >> 5, lq = idx & 31;
            float4 v = *(const float4*)(qkv + qbase + (size_t)(k0 + r) * E3 + 128 + lq * 4);
            uint32_t o = sb + OFF_K + (uint32_t)r * 512 + (uint32_t)((lq ^ (r & 7)) * 16);
            sts128(o, f2tf32(v.x), f2tf32(v.y), f2tf32(v.z), f2tf32(v.w));
        }
        const float* vsrc = vt + (size_t)bh * DHEAD * S_LEN + k0;
#pragma unroll
        for (int it = 0; it < 8; it++) {
            int idx = tid + it * 256;
            int dh = idx >> 4, kq = idx & 15;
            float4 v = *(const float4*)(vsrc + (size_t)dh * S_LEN + kq * 4);
            sts128(vbuf + (uint32_t)dh * 272 + (uint32_t)kq * 16,
                   __float_as_uint(v.x), __float_as_uint(v.y),
                   __float_as_uint(v.z), __float_as_uint(v.w));
        }
        __syncthreads();

        const bool active = (k0 <= q0 + w * 16 + 15);
        if (active) {
            float sf[8][4];
#pragma unroll
            for (int n = 0; n < 8; n++)
#pragma unroll
                for (int j = 0; j < 4; j++) sf[n][j] = 0.0f;

#pragma unroll
            for (int c = 0; c < 16; c++) {
                uint32_t af[4];
                uint32_t qa = (2u * c + kqA) ^ swm;
                ldsm4(af, sb + OFF_Q + (uint32_t)(w * 16 + rA) * 512 + qa * 16);
#pragma unroll
                for (int p = 0; p < 4; p++) {
                    uint32_t bf[4];
                    uint32_t qb = (2u * c + kqB) ^ swm;
                    ldsm4(bf, sb + OFF_K + (uint32_t)(p * 16 + rB) * 512 + qb * 16);
                    mma_tf32(sf[2 * p],     af, bf[0], bf[1]);
                    mma_tf32(sf[2 * p + 1], af, bf[2], bf[3]);
                }
            }

            if (k0 + FBN - 1 > q0 + w * 16) {
#pragma unroll
                for (int n = 0; n < 8; n++) {
                    int col = k0 + n * 8 + qw * 2;
                    if (col > row0g)     sf[n][0] = -1e30f;
                    if (col + 1 > row0g) sf[n][1] = -1e30f;
                    if (col > row1g)     sf[n][2] = -1e30f;
                    if (col + 1 > row1g) sf[n][3] = -1e30f;
                }
            }

            float mx0 = -1e30f, mx1 = -1e30f;
#pragma unroll
            for (int n = 0; n < 8; n++) {
                mx0 = fmaxf(mx0, fmaxf(sf[n][0], sf[n][1]));
                mx1 = fmaxf(mx1, fmaxf(sf[n][2], sf[n][3]));
            }
            mx0 = fmaxf(mx0, __shfl_xor_sync(0xffffffffu, mx0, 1));
            mx0 = fmaxf(mx0, __shfl_xor_sync(0xffffffffu, mx0, 2));
            mx1 = fmaxf(mx1, __shfl_xor_sync(0xffffffffu, mx1, 1));
            mx1 = fmaxf(mx1, __shfl_xor_sync(0xffffffffu, mx1, 2));
            const float mn0 = fmaxf(mr0, mx0);
            const float mn1 = fmaxf(mr1, mx1);
            const float cor0 = __expf(mr0 - mn0);
            const float cor1 = __expf(mr1 - mn1);
            float rs0 = 0.0f, rs1 = 0.0f;
#pragma unroll
            for (int n = 0; n < 8; n++) {
                sf[n][0] = __expf(sf[n][0] - mn0);
                sf[n][1] = __expf(sf[n][1] - mn0);
                sf[n][2] = __expf(sf[n][2] - mn1);
                sf[n][3] = __expf(sf[n][3] - mn1);
                rs0 += sf[n][0] + sf[n][1];
                rs1 += sf[n][2] + sf[n][3];
            }
            rs0 += __shfl_xor_sync(0xffffffffu, rs0, 1);
            rs0 += __shfl_xor_sync(0xffffffffu, rs0, 2);
            rs1 += __shfl_xor_sync(0xffffffffu, rs1, 1);
            rs1 += __shfl_xor_sync(0xffffffffu, rs1, 2);
            lr0 = lr0 * cor0 + rs0;  mr0 = mn0;
            lr1 = lr1 * cor1 + rs1;  mr1 = mn1;
#pragma unroll
            for (int n = 0; n < 16; n++) {
                o_acc[n][0] *= cor0; o_acc[n][1] *= cor0;
                o_acc[n][2] *= cor1; o_acc[n][3] *= cor1;
            }

            const uint32_t pr0 = sb + OFF_P + (uint32_t)(w * 16 + g) * 272
                               + (uint32_t)qw * 8;
#pragma unroll
            for (int n = 0; n < 8; n++) {
                sts64(pr0 + (uint32_t)n * 32, f2tf32(sf[n][0]), f2tf32(sf[n][1]));
                sts64(pr0 + 8 * 272 + (uint32_t)n * 32,
                      f2tf32(sf[n][2]), f2tf32(sf[n][3]));
            }
        }
        __syncthreads();

        if (active) {
#pragma unroll
            for (int c = 0; c < 8; c++) {
                uint32_t af[4];
                ldsm4(af, sb + OFF_P + (uint32_t)(w * 16 + rA) * 272
                          + (2u * c + kqA) * 16);
#pragma unroll
                for (int p = 0; p < 8; p++) {
                    uint32_t bf[4];
                    ldsm4(bf, vbuf + (uint32_t)(p * 16 + rB) * 272
                              + (2u * c + kqB) * 16);
                    mma_tf32(o_acc[2 * p],     af, bf[0], bf[1]);
                    mma_tf32(o_acc[2 * p + 1], af, bf[2], bf[3]);
                }
            }
        }
    }

    // Epilogue: normalize + ROUND TO TF32 (GEMM2 consumes this directly)
    const float inv0 = 1.0f / lr0;
    const float inv1 = 1.0f / lr1;
#pragma unroll
    for (int n = 0; n < 16; n++) {
        const int col = h * DHEAD + n * 8 + qw * 2;
        float* p0 = out + (size_t)((size_t)b * S_LEN + row0g) * D_MODEL + col;
        float* p1 = out + (size_t)((size_t)b * S_LEN + row1g) * D_MODEL + col;
        uint2 a = make_uint2(f2tf32(o_acc[n][0] * inv0), f2tf32(o_acc[n][1] * inv0));
        uint2 c = make_uint2(f2tf32(o_acc[n][2] * inv1), f2tf32(o_acc[n][3] * inv1));
        *(uint2*)p0 = a;
        *(uint2*)p1 = c;
    }
}

// ---------------------------------------------------------------------------
extern "C" void kernel_launch(void* const* d_in, const int* in_sizes, int n_in,
                              void* d_out, int out_size) {
    const float* x     = (const float*)d_in[0];  // [B,S,D]
    const float* w_in  = (const float*)d_in[1];  // [3*H*DH, D]
    const float* w_out = (const float*)d_in[2];  // [D, H*DH]
    float* out = (float*)d_out;                  // [B,S,D]

    float *qkv, *attn, *vt, *xtf, *wintf, *wouttf;
    cudaGetSymbolAddress((void**)&qkv, g_qkv);
    cudaGetSymbolAddress((void**)&attn, g_attn);
    cudaGetSymbolAddress((void**)&vt, g_vt);
    cudaGetSymbolAddress((void**)&xtf, g_xtf);
    cudaGetSymbolAddress((void**)&wintf, g_wintf);
    cudaGetSymbolAddress((void**)&wouttf, g_wouttf);

    cudaFuncSetAttribute(gemm_mma, cudaFuncAttributeMaxDynamicSharedMemorySize,
                         GEMM_SMEM);
    cudaFuncSetAttribute(flash_attn_mma, cudaFuncAttributeMaxDynamicSharedMemorySize,
                         FA_SMEM);

    // 0) tf32-round GEMM operands
    const int n4x = M_TOK * D_MODEL / 4;
    const int n4wi = E3 * D_MODEL / 4;
    const int n4wo = D_MODEL * D_MODEL / 4;
    cvt_tf32<<<(n4x + 255) / 256, 256>>>(x, xtf, n4x);
    cvt_tf32<<<(n4wi + 255) / 256, 256>>>(w_in, wintf, n4wi);
    cvt_tf32<<<(n4wo + 255) / 256, 256>>>(w_out, wouttf, n4wo);

    // 1) QKV projection
    dim3 g1(E3 / 128, M_TOK / 128);
    gemm_mma<<<g1, 256, GEMM_SMEM>>>(xtf, wintf, qkv, M_TOK, E3, D_MODEL);

    // 2) V transpose pre-pass
    dim3 gt(S_LEN / 32, DHEAD / 32, BATCH * NH);
    transpose_v<<<gt, 256>>>(qkv, vt);

    // 3) Causal flash attention (tensor cores); output tf32-rounded
    dim3 g2(S_LEN / FBM, BATCH * NH);
    flash_attn_mma<<<g2, 256, FA_SMEM>>>(qkv, vt, attn);

    // 4) Output projection
    dim3 g3(D_MODEL / 128, M_TOK / 128);
    gemm_mma<<<g3, 256, GEMM_SMEM>>>(attn, wouttf, out, M_TOK, D_MODEL, D_MODEL);
}

// round 6
// speedup vs baseline: 6.4975x; 1.0559x over previous
#include <cuda_runtime.h>
#include <cstdint>

// Problem constants
#define BATCH   2
#define S_LEN   2048
#define D_MODEL 2048
#define NH      16
#define DHEAD   128
#define M_TOK   (BATCH * S_LEN)     // 4096 tokens
#define E3      (3 * NH * DHEAD)    // 6144 qkv features

// Scratch (alloc-free rule: __device__ globals)
__device__ float g_qkv[(size_t)M_TOK * E3];                // [4096, 6144] (tf32)
__device__ float g_attn[(size_t)M_TOK * D_MODEL];          // [4096, 2048] (tf32)
__device__ float g_vt[(size_t)BATCH * NH * DHEAD * S_LEN]; // [b,h,dh,s]  (tf32)
__device__ float g_xtf[(size_t)M_TOK * D_MODEL];           // tf32-rounded x
__device__ float g_wintf[(size_t)E3 * D_MODEL];            // tf32-rounded w_in
__device__ float g_wouttf[(size_t)D_MODEL * D_MODEL];      // tf32-rounded w_out

// ===========================================================================
// PTX helpers (generic sm_80+ only — toolchain targets plain compute_103)
// ===========================================================================
__device__ __forceinline__ uint32_t smem_u32(const void* p) {
    uint32_t a;
    asm("{ .reg .u64 t; cvta.to.shared.u64 t, %1; cvt.u32.u64 %0, t; }"
        : "=r"(a) : "l"(p));
    return a;
}

__device__ __forceinline__ uint32_t f2tf32(float x) {
    uint32_t r;
    asm("cvt.rn.tf32.f32 %0, %1;" : "=r"(r) : "f"(x));
    return r;
}

__device__ __forceinline__ void ldsm4(uint32_t* r, uint32_t addr) {
    asm volatile("ldmatrix.sync.aligned.m8n8.x4.shared.b16 {%0,%1,%2,%3}, [%4];"
                 : "=r"(r[0]), "=r"(r[1]), "=r"(r[2]), "=r"(r[3]) : "r"(addr));
}

__device__ __forceinline__ void mma_tf32(float* c, const uint32_t* a,
                                         uint32_t b0, uint32_t b1) {
    asm volatile(
        "mma.sync.aligned.m16n8k8.row.col.f32.tf32.tf32.f32 "
        "{%0,%1,%2,%3}, {%4,%5,%6,%7}, {%8,%9}, {%0,%1,%2,%3};"
        : "+f"(c[0]), "+f"(c[1]), "+f"(c[2]), "+f"(c[3])
        : "r"(a[0]), "r"(a[1]), "r"(a[2]), "r"(a[3]), "r"(b0), "r"(b1));
}

__device__ __forceinline__ void sts64(uint32_t addr, uint32_t x, uint32_t y) {
    asm volatile("st.shared.v2.b32 [%0], {%1,%2};" :: "r"(addr), "r"(x), "r"(y));
}

__device__ __forceinline__ void cp16(uint32_t dst, const void* src) {
    asm volatile("cp.async.cg.shared.global [%0], [%1], 16;"
                 :: "r"(dst), "l"(src));
}
#define CP_COMMIT() asm volatile("cp.async.commit_group;" ::: "memory")
#define CP_WAIT1()  asm volatile("cp.async.wait_group 1;" ::: "memory")
#define CP_WAIT0()  asm volatile("cp.async.wait_group 0;" ::: "memory")

// ===========================================================================
// tf32 rounding pre-pass (elementwise, vectorized)
// ===========================================================================
__global__ __launch_bounds__(256)
void cvt_tf32(const float* __restrict__ src, float* __restrict__ dst, int n4) {
    int i = blockIdx.x * 256 + threadIdx.x;
    if (i < n4) {
        float4 v = ((const float4*)src)[i];
        ((uint4*)dst)[i] = make_uint4(f2tf32(v.x), f2tf32(v.y),
                                      f2tf32(v.z), f2tf32(v.w));
    }
}

// ===========================================================================
// cp.async 3-stage tf32 GEMM: C[M,N] = A[M,K] * B[N,K]^T  (R5 WIN, protected)
// ROUND_OUT: round C to tf32 in epilogue (for qkv feeding FA).
// ===========================================================================
#define NSTAGE 3
#define STAGE_B 32768
#define GEMM_SMEM (NSTAGE * STAGE_B)

template <int ROUND_OUT>
__global__ __launch_bounds__(256, 2)
void gemm_mma(const float* __restrict__ A, const float* __restrict__ B,
              float* __restrict__ C, int M, int N, int K) {
    extern __shared__ unsigned char dsm[];
    const uint32_t sbase = smem_u32(dsm);

    const int tid  = threadIdx.x;
    const int lane = tid & 31;
    const int wid  = tid >> 5;
    const int wm   = wid & 3;
    const int wn   = wid >> 2;
    const int bm   = blockIdx.y * 128;
    const int bn   = blockIdx.x * 128;

    const int lrow = tid >> 3;
    const int lq   = tid & 7;
    const float* Ag = A + (size_t)(bm + lrow) * K + lq * 4;
    const float* Bg = B + (size_t)(bn + lrow) * K + lq * 4;
    const uint32_t sq = (uint32_t)((lq ^ (lrow & 7)) * 16);
    const uint32_t stsA = sbase + (uint32_t)lrow * 128 + sq;
    const uint32_t stsB = stsA + 16384;

    const int tA = lane >> 3;
    const int mA = wm * 32 + ((tA & 1) << 3) + (lane & 7);
    const uint32_t kqA = (uint32_t)(tA >> 1);
    const int nB = wn * 64 + ((lane >> 4) << 3) + (lane & 7);
    const uint32_t kqB = (uint32_t)((lane >> 3) & 1);
    const uint32_t swm = (uint32_t)(lane & 7);

    float cacc[2][8][4];
#pragma unroll
    for (int t = 0; t < 2; t++)
#pragma unroll
        for (int n = 0; n < 8; n++)
#pragma unroll
            for (int j = 0; j < 4; j++) cacc[t][n][j] = 0.0f;

    const int NC = K >> 5;

#pragma unroll
    for (int s = 0; s < NSTAGE - 1; s++) {
        const uint32_t so = (uint32_t)s * STAGE_B;
        const int k0 = s * 32;
#pragma unroll
        for (int it = 0; it < 4; it++) {
            cp16(stsA + so + it * 32 * 128u, Ag + k0 + (size_t)it * 32 * K);
            cp16(stsB + so + it * 32 * 128u, Bg + k0 + (size_t)it * 32 * K);
        }
        CP_COMMIT();
    }

    for (int ch = 0; ch < NC; ch++) {
        CP_WAIT1();
        __syncthreads();

        if (ch + NSTAGE - 1 < NC) {
            const uint32_t so = (uint32_t)((ch + NSTAGE - 1) % NSTAGE) * STAGE_B;
            const int k0 = (ch + NSTAGE - 1) * 32;
#pragma unroll
            for (int it = 0; it < 4; it++) {
                cp16(stsA + so + it * 32 * 128u, Ag + k0 + (size_t)it * 32 * K);
                cp16(stsB + so + it * 32 * 128u, Bg + k0 + (size_t)it * 32 * K);
            }
        }
        CP_COMMIT();

        const uint32_t aBase = sbase + (uint32_t)(ch % NSTAGE) * STAGE_B;
        const uint32_t bBase = aBase + 16384;
#pragma unroll
        for (int c = 0; c < 4; c++) {
            uint32_t afr[2][4];
#pragma unroll
            for (int t = 0; t < 2; t++) {
                uint32_t q = (2u * c + kqA) ^ swm;
                ldsm4(afr[t], aBase + (uint32_t)(mA + 16 * t) * 128 + q * 16);
            }
            uint32_t bfr[4][4];
#pragma unroll
            for (int p = 0; p < 4; p++) {
                uint32_t q = (2u * c + kqB) ^ swm;
                ldsm4(bfr[p], bBase + (uint32_t)(nB + 16 * p) * 128 + q * 16);
            }
#pragma unroll
            for (int t = 0; t < 2; t++)
#pragma unroll
                for (int p = 0; p < 4; p++) {
                    mma_tf32(cacc[t][2 * p],     afr[t], bfr[p][0], bfr[p][1]);
                    mma_tf32(cacc[t][2 * p + 1], afr[t], bfr[p][2], bfr[p][3]);
                }
        }
    }
    CP_WAIT0();

    const int g = lane >> 2;
    const int w2 = (lane & 3) * 2;
#pragma unroll
    for (int t = 0; t < 2; t++) {
        const int row0 = bm + wm * 32 + t * 16 + g;
        const int col0 = bn + wn * 64 + w2;
#pragma unroll
        for (int n = 0; n < 8; n++) {
            float* p0 = C + (size_t)row0 * N + col0 + n * 8;
            float* p1 = C + (size_t)(row0 + 8) * N + col0 + n * 8;
            if (ROUND_OUT) {
                *(uint2*)p0 = make_uint2(f2tf32(cacc[t][n][0]), f2tf32(cacc[t][n][1]));
                *(uint2*)p1 = make_uint2(f2tf32(cacc[t][n][2]), f2tf32(cacc[t][n][3]));
            } else {
                *(float2*)p0 = make_float2(cacc[t][n][0], cacc[t][n][1]);
                *(float2*)p1 = make_float2(cacc[t][n][2], cacc[t][n][3]);
            }
        }
    }
}

// ===========================================================================
// V transpose pre-pass: g_qkv V-slices -> g_vt[b,h,dh,s] (already tf32).
// ===========================================================================
__global__ __launch_bounds__(256)
void transpose_v(const float* __restrict__ qkv, float* __restrict__ vt) {
    __shared__ float t[32][33];
    const int bh = blockIdx.z;
    const int b = bh >> 4, h = bh & 15;
    const int s0 = blockIdx.x * 32;
    const int d0 = blockIdx.y * 32;
    const int tx = threadIdx.x & 31;
    const int ty = threadIdx.x >> 5;

    const float* src = qkv + (size_t)b * S_LEN * E3 + (size_t)h * 384 + 256;
#pragma unroll
    for (int i = ty; i < 32; i += 8)
        t[i][tx] = src[(size_t)(s0 + i) * E3 + d0 + tx];
    __syncthreads();
    float* dst = vt + ((size_t)bh * DHEAD + d0) * S_LEN + s0;
#pragma unroll
    for (int i = ty; i < 32; i += 8)
        dst[(size_t)i * S_LEN + tx] = t[tx][i];
}

// ===========================================================================
// Flash attention, mma.sync tf32, fully cp.async-pipelined. Causal.
// All inputs pre-rounded tf32; scale applied to S-fragments post-MMA.
// CTA: 128 q-rows; 8 warps (warp w = m16 band); kv tiles 64, K/Vt double-buf.
// Smem layout (all quad-xor swizzled except noted):
//   Q  128x512B @ 0        (65536)
//   K0  64x512B @ 65536    K1 @ 98304      (32768 each)
//   V0 128x256B @ 131072   V1 @ 163840     (32768 each)
//   P  128x256B @ 196608                   (32768)
// Total 229376. Block order reversed so heavy (large-q0) CTAs launch first.
// ===========================================================================
#define FBM 128
#define FBN 64
#define FQ_OFF 0u
#define FK_OFF 65536u
#define FV_OFF 131072u
#define FP_OFF 196608u
#define FA_SMEM 229376

__global__ __launch_bounds__(256, 1)
void flash_attn_mma(const float* __restrict__ qkv, const float* __restrict__ vt,
                    float* __restrict__ out) {
    extern __shared__ unsigned char fsm[];
    const uint32_t sb = smem_u32(fsm);
    const int tid = threadIdx.x;
    const int lane = tid & 31;
    const int w = tid >> 5;
    const int bh = blockIdx.y;
    const int b = bh >> 4, h = bh & 15;
    const int q0 = ((int)gridDim.x - 1 - (int)blockIdx.x) * FBM;  // heavy first

    const float scale = 0.08838834764831845f;  // 1/sqrt(128)
    const size_t qbase = (size_t)b * S_LEN * E3 + (size_t)h * 384;
    const float* vsrc0 = vt + (size_t)bh * DHEAD * S_LEN;

    // cp.async staging indices
    const int qr = tid >> 3, qq = tid & 7;          // Q: 32 quads/row, 8 thr/row
    const int kr = tid >> 3, kq8 = tid & 7;         // K: rows of 512B
    const int vdh = tid >> 1, vq2 = (tid & 1) * 8;  // Vt: 16 quads/row, 2 thr/row

    // Prologue: Q (16/thr) + K(0) + Vt(0)
#pragma unroll
    for (int it = 0; it < 16; it++) {
        int idx = tid + it * 256;
        int r = idx >> 5, lq = idx & 31;
        cp16(sb + FQ_OFF + (uint32_t)r * 512 + (uint32_t)((lq ^ (r & 7)) * 16),
             qkv + qbase + (size_t)(q0 + r) * E3 + lq * 4);
    }
#pragma unroll
    for (int it = 0; it < 2; it++) {
        int r = kr + it * 32;
        int lq = kq8 * 4 + 0;  // 4 quads per thread, contiguous group of 64B? no:
        (void)lq;
    }
    // K(0): 64 rows x 32 quads = 2048 cp16 / 256 thr = 8 each
#pragma unroll
    for (int it = 0; it < 8; it++) {
        int idx = tid + it * 256;
        int r = idx >> 5, lq = idx & 31;
        cp16(sb + FK_OFF + (uint32_t)r * 512 + (uint32_t)((lq ^ (r & 7)) * 16),
             qkv + qbase + (size_t)r * E3 + 128 + lq * 4);
    }
    // Vt(0): 128 rows x 16 quads = 2048 cp16 / 256 thr = 8 each
#pragma unroll
    for (int it = 0; it < 8; it++) {
        int idx = tid + it * 256;
        int dh = idx >> 4, kq = idx & 15;
        cp16(sb + FV_OFF + (uint32_t)dh * 256 + (uint32_t)((kq ^ (dh & 7)) * 16),
             vsrc0 + (size_t)dh * S_LEN + kq * 4);
    }
    CP_COMMIT();

    // ldmatrix per-lane indices
    const int tA = lane >> 3;
    const int rA = ((tA & 1) << 3) + (lane & 7);
    const uint32_t kqA = (uint32_t)(tA >> 1);
    const int rB = ((lane >> 4) << 3) + (lane & 7);
    const uint32_t kqB = (uint32_t)((lane >> 3) & 1);
    const uint32_t swm = (uint32_t)(lane & 7);
    const int g = lane >> 2;
    const int qw = lane & 3;

    float o_acc[16][4];
#pragma unroll
    for (int n = 0; n < 16; n++)
#pragma unroll
        for (int j = 0; j < 4; j++) o_acc[n][j] = 0.0f;
    float mr0 = -1e30f, mr1 = -1e30f, lr0 = 0.0f, lr1 = 0.0f;

    const int row0g = q0 + w * 16 + g;
    const int row1g = row0g + 8;

    const int nkt = q0 / FBN + 2;
    for (int kb = 0; kb < nkt; kb++) {
        const int k0 = kb * FBN;
        const uint32_t kbuf = sb + FK_OFF + (uint32_t)(kb & 1) * 32768u;
        const uint32_t vbuf = sb + FV_OFF + (uint32_t)(kb & 1) * 32768u;

        CP_WAIT0();
        __syncthreads();   // tile kb data visible; all warps done with prev PV

        // Issue loads for tile kb+1 (overlap with this tile's compute)
        if (kb + 1 < nkt) {
            const int kn = k0 + FBN;
            const uint32_t kbufn = sb + FK_OFF + (uint32_t)((kb + 1) & 1) * 32768u;
            const uint32_t vbufn = sb + FV_OFF + (uint32_t)((kb + 1) & 1) * 32768u;
#pragma unroll
            for (int it = 0; it < 8; it++) {
                int idx = tid + it * 256;
                int r = idx >> 5, lq = idx & 31;
                cp16(kbufn + (uint32_t)r * 512 + (uint32_t)((lq ^ (r & 7)) * 16),
                     qkv + qbase + (size_t)(kn + r) * E3 + 128 + lq * 4);
            }
#pragma unroll
            for (int it = 0; it < 8; it++) {
                int idx = tid + it * 256;
                int dh = idx >> 4, kq = idx & 15;
                cp16(vbufn + (uint32_t)dh * 256 + (uint32_t)((kq ^ (dh & 7)) * 16),
                     vsrc0 + (size_t)dh * S_LEN + kn + kq * 4);
            }
        }
        CP_COMMIT();

        const bool active = (k0 <= q0 + w * 16 + 15);
        if (active) {
            // S = Q * K^T : m16 x n64 x k128
            float sf[8][4];
#pragma unroll
            for (int n = 0; n < 8; n++)
#pragma unroll
                for (int j = 0; j < 4; j++) sf[n][j] = 0.0f;

#pragma unroll
            for (int c = 0; c < 16; c++) {
                uint32_t af[4];
                uint32_t qa = (2u * c + kqA) ^ swm;
                ldsm4(af, sb + FQ_OFF + (uint32_t)(w * 16 + rA) * 512 + qa * 16);
#pragma unroll
                for (int p = 0; p < 4; p++) {
                    uint32_t bf[4];
                    uint32_t qb = (2u * c + kqB) ^ swm;
                    ldsm4(bf, kbuf + (uint32_t)(p * 16 + rB) * 512 + qb * 16);
                    mma_tf32(sf[2 * p],     af, bf[0], bf[1]);
                    mma_tf32(sf[2 * p + 1], af, bf[2], bf[3]);
                }
            }

            // Apply softmax scale (folded out of Q), then causal mask
#pragma unroll
            for (int n = 0; n < 8; n++)
#pragma unroll
                for (int j = 0; j < 4; j++) sf[n][j] *= scale;

            if (k0 + FBN - 1 > q0 + w * 16) {
#pragma unroll
                for (int n = 0; n < 8; n++) {
                    int col = k0 + n * 8 + qw * 2;
                    if (col > row0g)     sf[n][0] = -1e30f;
                    if (col + 1 > row0g) sf[n][1] = -1e30f;
                    if (col > row1g)     sf[n][2] = -1e30f;
                    if (col + 1 > row1g) sf[n][3] = -1e30f;
                }
            }

            // Online softmax
            float mx0 = -1e30f, mx1 = -1e30f;
#pragma unroll
            for (int n = 0; n < 8; n++) {
                mx0 = fmaxf(mx0, fmaxf(sf[n][0], sf[n][1]));
                mx1 = fmaxf(mx1, fmaxf(sf[n][2], sf[n][3]));
            }
            mx0 = fmaxf(mx0, __shfl_xor_sync(0xffffffffu, mx0, 1));
            mx0 = fmaxf(mx0, __shfl_xor_sync(0xffffffffu, mx0, 2));
            mx1 = fmaxf(mx1, __shfl_xor_sync(0xffffffffu, mx1, 1));
            mx1 = fmaxf(mx1, __shfl_xor_sync(0xffffffffu, mx1, 2));
            const float mn0 = fmaxf(mr0, mx0);
            const float mn1 = fmaxf(mr1, mx1);
            const float cor0 = __expf(mr0 - mn0);
            const float cor1 = __expf(mr1 - mn1);
            float rs0 = 0.0f, rs1 = 0.0f;
#pragma unroll
            for (int n = 0; n < 8; n++) {
                sf[n][0] = __expf(sf[n][0] - mn0);
                sf[n][1] = __expf(sf[n][1] - mn0);
                sf[n][2] = __expf(sf[n][2] - mn1);
                sf[n][3] = __expf(sf[n][3] - mn1);
                rs0 += sf[n][0] + sf[n][1];
                rs1 += sf[n][2] + sf[n][3];
            }
            rs0 += __shfl_xor_sync(0xffffffffu, rs0, 1);
            rs0 += __shfl_xor_sync(0xffffffffu, rs0, 2);
            rs1 += __shfl_xor_sync(0xffffffffu, rs1, 1);
            rs1 += __shfl_xor_sync(0xffffffffu, rs1, 2);
            lr0 = lr0 * cor0 + rs0;  mr0 = mn0;
            lr1 = lr1 * cor1 + rs1;  mr1 = mn1;
#pragma unroll
            for (int n = 0; n < 16; n++) {
                o_acc[n][0] *= cor0; o_acc[n][1] *= cor0;
                o_acc[n][2] *= cor1; o_acc[n][3] *= cor1;
            }

            // Write P (tf32) swizzled: row r, quad qd -> qd^(r&7)
            {
                const int r0 = w * 16 + g;
                const uint32_t base0 = sb + FP_OFF + (uint32_t)r0 * 256;
                const uint32_t base1 = base0 + 8 * 256;
                const uint32_t half = (uint32_t)(qw >> 1);
                const uint32_t byte8 = (uint32_t)(qw & 1) * 8;
#pragma unroll
                for (int n = 0; n < 8; n++) {
                    uint32_t qd = ((uint32_t)(2 * n) + half) ^ (uint32_t)(g & 7);
                    sts64(base0 + qd * 16 + byte8, f2tf32(sf[n][0]), f2tf32(sf[n][1]));
                    sts64(base1 + qd * 16 + byte8, f2tf32(sf[n][2]), f2tf32(sf[n][3]));
                }
            }
        }
        __syncthreads();

        if (active) {
            // O += P * Vt^T : m16 x n128 x k64
#pragma unroll
            for (int c = 0; c < 8; c++) {
                uint32_t af[4];
                ldsm4(af, sb + FP_OFF + (uint32_t)(w * 16 + rA) * 256
                          + ((2u * c + kqA) ^ swm) * 16);
#pragma unroll
                for (int p = 0; p < 8; p++) {
                    uint32_t bf[4];
                    ldsm4(bf, vbuf + (uint32_t)(p * 16 + rB) * 256
                              + ((2u * c + kqB) ^ swm) * 16);
                    mma_tf32(o_acc[2 * p],     af, bf[0], bf[1]);
                    mma_tf32(o_acc[2 * p + 1], af, bf[2], bf[3]);
                }
            }
        }
    }

    // Epilogue: normalize + round to tf32 (GEMM2 consumes directly)
    const float inv0 = 1.0f / lr0;
    const float inv1 = 1.0f / lr1;
#pragma unroll
    for (int n = 0; n < 16; n++) {
        const int col = h * DHEAD + n * 8 + qw * 2;
        float* p0 = out + (size_t)((size_t)b * S_LEN + row0g) * D_MODEL + col;
        float* p1 = out + (size_t)((size_t)b * S_LEN + row1g) * D_MODEL + col;
        *(uint2*)p0 = make_uint2(f2tf32(o_acc[n][0] * inv0), f2tf32(o_acc[n][1] * inv0));
        *(uint2*)p1 = make_uint2(f2tf32(o_acc[n][2] * inv1), f2tf32(o_acc[n][3] * inv1));
    }
}

// ---------------------------------------------------------------------------
extern "C" void kernel_launch(void* const* d_in, const int* in_sizes, int n_in,
                              void* d_out, int out_size) {
    const float* x     = (const float*)d_in[0];  // [B,S,D]
    const float* w_in  = (const float*)d_in[1];  // [3*H*DH, D]
    const float* w_out = (const float*)d_in[2];  // [D, H*DH]
    float* out = (float*)d_out;                  // [B,S,D]

    float *qkv, *attn, *vt, *xtf, *wintf, *wouttf;
    cudaGetSymbolAddress((void**)&qkv, g_qkv);
    cudaGetSymbolAddress((void**)&attn, g_attn);
    cudaGetSymbolAddress((void**)&vt, g_vt);
    cudaGetSymbolAddress((void**)&xtf, g_xtf);
    cudaGetSymbolAddress((void**)&wintf, g_wintf);
    cudaGetSymbolAddress((void**)&wouttf, g_wouttf);

    cudaFuncSetAttribute(gemm_mma<1>, cudaFuncAttributeMaxDynamicSharedMemorySize,
                         GEMM_SMEM);
    cudaFuncSetAttribute(gemm_mma<0>, cudaFuncAttributeMaxDynamicSharedMemorySize,
                         GEMM_SMEM);
    cudaFuncSetAttribute(flash_attn_mma, cudaFuncAttributeMaxDynamicSharedMemorySize,
                         FA_SMEM);

    // 0) tf32-round GEMM operands
    const int n4x = M_TOK * D_MODEL / 4;
    const int n4wi = E3 * D_MODEL / 4;
    const int n4wo = D_MODEL * D_MODEL / 4;
    cvt_tf32<<<(n4x + 255) / 256, 256>>>(x, xtf, n4x);
    cvt_tf32<<<(n4wi + 255) / 256, 256>>>(w_in, wintf, n4wi);
    cvt_tf32<<<(n4wo + 255) / 256, 256>>>(w_out, wouttf, n4wo);

    // 1) QKV projection (output rounded to tf32)
    dim3 g1(E3 / 128, M_TOK / 128);
    gemm_mma<1><<<g1, 256, GEMM_SMEM>>>(xtf, wintf, qkv, M_TOK, E3, D_MODEL);

    // 2) V transpose pre-pass
    dim3 gt(S_LEN / 32, DHEAD / 32, BATCH * NH);
    transpose_v<<<gt, 256>>>(qkv, vt);

    // 3) Causal flash attention (async-pipelined); output tf32-rounded
    dim3 g2(S_LEN / FBM, BATCH * NH);
    flash_attn_mma<<<g2, 256, FA_SMEM>>>(qkv, vt, attn);

    // 4) Output projection (full fp32 output)
    dim3 g3(D_MODEL / 128, M_TOK / 128);
    gemm_mma<0><<<g3, 256, GEMM_SMEM>>>(attn, wouttf, out, M_TOK, D_MODEL, D_MODEL);
}

// round 7
// speedup vs baseline: 6.7442x; 1.0380x over previous
#include <cuda_runtime.h>
#include <cstdint>

// Problem constants
#define BATCH   2
#define S_LEN   2048
#define D_MODEL 2048
#define NH      16
#define DHEAD   128
#define M_TOK   (BATCH * S_LEN)     // 4096 tokens
#define E3      (3 * NH * DHEAD)    // 6144 qkv features

// Scratch (alloc-free rule: __device__ globals)
__device__ float g_qkv[(size_t)M_TOK * E3];                // [4096, 6144] (tf32)
__device__ float g_attn[(size_t)M_TOK * D_MODEL];          // [4096, 2048] (tf32)
__device__ float g_vt[(size_t)BATCH * NH * DHEAD * S_LEN]; // [b,h,dh,s]  (tf32)
__device__ float g_xtf[(size_t)M_TOK * D_MODEL];           // tf32-rounded x
__device__ float g_wintf[(size_t)E3 * D_MODEL];            // tf32-rounded w_in
__device__ float g_wouttf[(size_t)D_MODEL * D_MODEL];      // tf32-rounded w_out

// ===========================================================================
// PTX helpers (generic sm_80+ only — toolchain targets plain compute_103)
// ===========================================================================
__device__ __forceinline__ uint32_t smem_u32(const void* p) {
    uint32_t a;
    asm("{ .reg .u64 t; cvta.to.shared.u64 t, %1; cvt.u32.u64 %0, t; }"
        : "=r"(a) : "l"(p));
    return a;
}

__device__ __forceinline__ uint32_t f2tf32(float x) {
    uint32_t r;
    asm("cvt.rn.tf32.f32 %0, %1;" : "=r"(r) : "f"(x));
    return r;
}

__device__ __forceinline__ void ldsm4(uint32_t* r, uint32_t addr) {
    asm volatile("ldmatrix.sync.aligned.m8n8.x4.shared.b16 {%0,%1,%2,%3}, [%4];"
                 : "=r"(r[0]), "=r"(r[1]), "=r"(r[2]), "=r"(r[3]) : "r"(addr));
}

__device__ __forceinline__ void mma_tf32(float* c, const uint32_t* a,
                                         uint32_t b0, uint32_t b1) {
    asm volatile(
        "mma.sync.aligned.m16n8k8.row.col.f32.tf32.tf32.f32 "
        "{%0,%1,%2,%3}, {%4,%5,%6,%7}, {%8,%9}, {%0,%1,%2,%3};"
        : "+f"(c[0]), "+f"(c[1]), "+f"(c[2]), "+f"(c[3])
        : "r"(a[0]), "r"(a[1]), "r"(a[2]), "r"(a[3]), "r"(b0), "r"(b1));
}

__device__ __forceinline__ void sts64(uint32_t addr, uint32_t x, uint32_t y) {
    asm volatile("st.shared.v2.b32 [%0], {%1,%2};" :: "r"(addr), "r"(x), "r"(y));
}

__device__ __forceinline__ void cp16(uint32_t dst, const void* src) {
    asm volatile("cp.async.cg.shared.global [%0], [%1], 16;"
                 :: "r"(dst), "l"(src));
}
#define CP_COMMIT() asm volatile("cp.async.commit_group;" ::: "memory")
#define CP_WAIT1()  asm volatile("cp.async.wait_group 1;" ::: "memory")
#define CP_WAIT0()  asm volatile("cp.async.wait_group 0;" ::: "memory")

// ===========================================================================
// tf32 rounding pre-pass (elementwise, vectorized)
// ===========================================================================
__global__ __launch_bounds__(256)
void cvt_tf32(const float* __restrict__ src, float* __restrict__ dst, int n4) {
    int i = blockIdx.x * 256 + threadIdx.x;
    if (i < n4) {
        float4 v = ((const float4*)src)[i];
        ((uint4*)dst)[i] = make_uint4(f2tf32(v.x), f2tf32(v.y),
                                      f2tf32(v.z), f2tf32(v.w));
    }
}

// ===========================================================================
// cp.async 3-stage tf32 GEMM v2: C[M,N] = A[M,K] * B[N,K]^T
// CTA tile 128x128, 128 threads (4 warps), warp tile 64x64 (2m x 2n grid).
// Per k-step: 8 LDSM.x4 per 32 MMA (1:4) — tensor pipe fed denser than the
// R5/R6 1:2.67 layout. Smem 3 x 32KB = 96KB -> 2 CTAs/SM.
// Inputs pre-rounded tf32. ROUND_OUT rounds C for downstream tf32 consumers.
// ===========================================================================
#define NSTAGE 3
#define STAGE_B 32768
#define GEMM_SMEM (NSTAGE * STAGE_B)

template <int ROUND_OUT>
__global__ __launch_bounds__(128, 2)
void gemm_mma(const float* __restrict__ A, const float* __restrict__ B,
              float* __restrict__ C, int M, int N, int K) {
    extern __shared__ unsigned char dsm[];
    const uint32_t sbase = smem_u32(dsm);

    const int tid  = threadIdx.x;
    const int lane = tid & 31;
    const int wid  = tid >> 5;      // 0..3
    const int wm   = wid & 1;       // m band (64 rows)
    const int wn   = wid >> 1;      // n band (64 cols)
    const int bm   = blockIdx.y * 128;
    const int bn   = blockIdx.x * 128;

    // cp.async staging: 128 thr; thread -> (row lrow + it*16, quad lq)
    const int lrow = tid >> 3;      // 0..15
    const int lq   = tid & 7;       // 0..7
    const float* Ag = A + (size_t)(bm + lrow) * K + lq * 4;
    const float* Bg = B + (size_t)(bn + lrow) * K + lq * 4;
    const uint32_t sq = (uint32_t)((lq ^ (lrow & 7)) * 16);
    const uint32_t stsA = sbase + (uint32_t)lrow * 128 + sq;
    const uint32_t stsB = stsA + 16384;

    // ldmatrix per-lane indices
    const int tA = lane >> 3;
    const int mA = wm * 64 + ((tA & 1) << 3) + (lane & 7);     // +16*t
    const uint32_t kqA = (uint32_t)(tA >> 1);
    const int nB = wn * 64 + ((lane >> 4) << 3) + (lane & 7);  // +16*p
    const uint32_t kqB = (uint32_t)((lane >> 3) & 1);
    const uint32_t swm = (uint32_t)(lane & 7);

    float cacc[4][8][4];
#pragma unroll
    for (int t = 0; t < 4; t++)
#pragma unroll
        for (int n = 0; n < 8; n++)
#pragma unroll
            for (int j = 0; j < 4; j++) cacc[t][n][j] = 0.0f;

    const int NC = K >> 5;

    // Prologue: stages 0..NSTAGE-2 (8 A + 8 B cp16 per thread per stage)
#pragma unroll
    for (int s = 0; s < NSTAGE - 1; s++) {
        const uint32_t so = (uint32_t)s * STAGE_B;
        const int k0 = s * 32;
#pragma unroll
        for (int it = 0; it < 8; it++) {
            cp16(stsA + so + it * 16 * 128u, Ag + k0 + (size_t)it * 16 * K);
            cp16(stsB + so + it * 16 * 128u, Bg + k0 + (size_t)it * 16 * K);
        }
        CP_COMMIT();
    }

    for (int ch = 0; ch < NC; ch++) {
        CP_WAIT1();
        __syncthreads();

        if (ch + NSTAGE - 1 < NC) {
            const uint32_t so = (uint32_t)((ch + NSTAGE - 1) % NSTAGE) * STAGE_B;
            const int k0 = (ch + NSTAGE - 1) * 32;
#pragma unroll
            for (int it = 0; it < 8; it++) {
                cp16(stsA + so + it * 16 * 128u, Ag + k0 + (size_t)it * 16 * K);
                cp16(stsB + so + it * 16 * 128u, Bg + k0 + (size_t)it * 16 * K);
            }
        }
        CP_COMMIT();

        const uint32_t aBase = sbase + (uint32_t)(ch % NSTAGE) * STAGE_B;
        const uint32_t bBase = aBase + 16384;
#pragma unroll
        for (int c = 0; c < 4; c++) {
            uint32_t afr[4][4];
#pragma unroll
            for (int t = 0; t < 4; t++) {
                uint32_t q = (2u * c + kqA) ^ swm;
                ldsm4(afr[t], aBase + (uint32_t)(mA + 16 * t) * 128 + q * 16);
            }
            uint32_t bfr[4][4];
#pragma unroll
            for (int p = 0; p < 4; p++) {
                uint32_t q = (2u * c + kqB) ^ swm;
                ldsm4(bfr[p], bBase + (uint32_t)(nB + 16 * p) * 128 + q * 16);
            }
#pragma unroll
            for (int t = 0; t < 4; t++)
#pragma unroll
                for (int p = 0; p < 4; p++) {
                    mma_tf32(cacc[t][2 * p],     afr[t], bfr[p][0], bfr[p][1]);
                    mma_tf32(cacc[t][2 * p + 1], afr[t], bfr[p][2], bfr[p][3]);
                }
        }
    }
    CP_WAIT0();

    const int g = lane >> 2;
    const int w2 = (lane & 3) * 2;
#pragma unroll
    for (int t = 0; t < 4; t++) {
        const int row0 = bm + wm * 64 + t * 16 + g;
        const int col0 = bn + wn * 64 + w2;
#pragma unroll
        for (int n = 0; n < 8; n++) {
            float* p0 = C + (size_t)row0 * N + col0 + n * 8;
            float* p1 = C + (size_t)(row0 + 8) * N + col0 + n * 8;
            if (ROUND_OUT) {
                *(uint2*)p0 = make_uint2(f2tf32(cacc[t][n][0]), f2tf32(cacc[t][n][1]));
                *(uint2*)p1 = make_uint2(f2tf32(cacc[t][n][2]), f2tf32(cacc[t][n][3]));
            } else {
                *(float2*)p0 = make_float2(cacc[t][n][0], cacc[t][n][1]);
                *(float2*)p1 = make_float2(cacc[t][n][2], cacc[t][n][3]);
            }
        }
    }
}

// ===========================================================================
// V transpose pre-pass: g_qkv V-slices -> g_vt[b,h,dh,s] (already tf32).
// ===========================================================================
__global__ __launch_bounds__(256)
void transpose_v(const float* __restrict__ qkv, float* __restrict__ vt) {
    __shared__ float t[32][33];
    const int bh = blockIdx.z;
    const int b = bh >> 4, h = bh & 15;
    const int s0 = blockIdx.x * 32;
    const int d0 = blockIdx.y * 32;
    const int tx = threadIdx.x & 31;
    const int ty = threadIdx.x >> 5;

    const float* src = qkv + (size_t)b * S_LEN * E3 + (size_t)h * 384 + 256;
#pragma unroll
    for (int i = ty; i < 32; i += 8)
        t[i][tx] = src[(size_t)(s0 + i) * E3 + d0 + tx];
    __syncthreads();
    float* dst = vt + ((size_t)bh * DHEAD + d0) * S_LEN + s0;
#pragma unroll
    for (int i = ty; i < 32; i += 8)
        dst[(size_t)i * S_LEN + tx] = t[tx][i];
}

// ===========================================================================
// Flash attention, mma.sync tf32, cp.async-pipelined (R6 WIN, protected).
// ===========================================================================
#define FBM 128
#define FBN 64
#define FQ_OFF 0u
#define FK_OFF 65536u
#define FV_OFF 131072u
#define FP_OFF 196608u
#define FA_SMEM 229376

__global__ __launch_bounds__(256, 1)
void flash_attn_mma(const float* __restrict__ qkv, const float* __restrict__ vt,
                    float* __restrict__ out) {
    extern __shared__ unsigned char fsm[];
    const uint32_t sb = smem_u32(fsm);
    const int tid = threadIdx.x;
    const int lane = tid & 31;
    const int w = tid >> 5;
    const int bh = blockIdx.y;
    const int b = bh >> 4, h = bh & 15;
    const int q0 = ((int)gridDim.x - 1 - (int)blockIdx.x) * FBM;  // heavy first

    const float scale = 0.08838834764831845f;  // 1/sqrt(128)
    const size_t qbase = (size_t)b * S_LEN * E3 + (size_t)h * 384;
    const float* vsrc0 = vt + (size_t)bh * DHEAD * S_LEN;

    // Prologue: Q + K(0) + Vt(0)
#pragma unroll
    for (int it = 0; it < 16; it++) {
        int idx = tid + it * 256;
        int r = idx >> 5, lq = idx & 31;
        cp16(sb + FQ_OFF + (uint32_t)r * 512 + (uint32_t)((lq ^ (r & 7)) * 16),
             qkv + qbase + (size_t)(q0 + r) * E3 + lq * 4);
    }
#pragma unroll
    for (int it = 0; it < 8; it++) {
        int idx = tid + it * 256;
        int r = idx >> 5, lq = idx & 31;
        cp16(sb + FK_OFF + (uint32_t)r * 512 + (uint32_t)((lq ^ (r & 7)) * 16),
             qkv + qbase + (size_t)r * E3 + 128 + lq * 4);
    }
#pragma unroll
    for (int it = 0; it < 8; it++) {
        int idx = tid + it * 256;
        int dh = idx >> 4, kq = idx & 15;
        cp16(sb + FV_OFF + (uint32_t)dh * 256 + (uint32_t)((kq ^ (dh & 7)) * 16),
             vsrc0 + (size_t)dh * S_LEN + kq * 4);
    }
    CP_COMMIT();

    const int tA = lane >> 3;
    const int rA = ((tA & 1) << 3) + (lane & 7);
    const uint32_t kqA = (uint32_t)(tA >> 1);
    const int rB = ((lane >> 4) << 3) + (lane & 7);
    const uint32_t kqB = (uint32_t)((lane >> 3) & 1);
    const uint32_t swm = (uint32_t)(lane & 7);
    const int g = lane >> 2;
    const int qw = lane & 3;

    float o_acc[16][4];
#pragma unroll
    for (int n = 0; n < 16; n++)
#pragma unroll
        for (int j = 0; j < 4; j++) o_acc[n][j] = 0.0f;
    float mr0 = -1e30f, mr1 = -1e30f, lr0 = 0.0f, lr1 = 0.0f;

    const int row0g = q0 + w * 16 + g;
    const int row1g = row0g + 8;

    const int nkt = q0 / FBN + 2;
    for (int kb = 0; kb < nkt; kb++) {
        const int k0 = kb * FBN;
        const uint32_t kbuf = sb + FK_OFF + (uint32_t)(kb & 1) * 32768u;
        const uint32_t vbuf = sb + FV_OFF + (uint32_t)(kb & 1) * 32768u;

        CP_WAIT0();
        __syncthreads();

        if (kb + 1 < nkt) {
            const int kn = k0 + FBN;
            const uint32_t kbufn = sb + FK_OFF + (uint32_t)((kb + 1) & 1) * 32768u;
            const uint32_t vbufn = sb + FV_OFF + (uint32_t)((kb + 1) & 1) * 32768u;
#pragma unroll
            for (int it = 0; it < 8; it++) {
                int idx = tid + it * 256;
                int r = idx >> 5, lq = idx & 31;
                cp16(kbufn + (uint32_t)r * 512 + (uint32_t)((lq ^ (r & 7)) * 16),
                     qkv + qbase + (size_t)(kn + r) * E3 + 128 + lq * 4);
            }
#pragma unroll
            for (int it = 0; it < 8; it++) {
                int idx = tid + it * 256;
                int dh = idx >> 4, kq = idx & 15;
                cp16(vbufn + (uint32_t)dh * 256 + (uint32_t)((kq ^ (dh & 7)) * 16),
                     vsrc0 + (size_t)dh * S_LEN + kn + kq * 4);
            }
        }
        CP_COMMIT();

        const bool active = (k0 <= q0 + w * 16 + 15);
        if (active) {
            float sf[8][4];
#pragma unroll
            for (int n = 0; n < 8; n++)
#pragma unroll
                for (int j = 0; j < 4; j++) sf[n][j] = 0.0f;

#pragma unroll
            for (int c = 0; c < 16; c++) {
                uint32_t af[4];
                uint32_t qa = (2u * c + kqA) ^ swm;
                ldsm4(af, sb + FQ_OFF + (uint32_t)(w * 16 + rA) * 512 + qa * 16);
#pragma unroll
                for (int p = 0; p < 4; p++) {
                    uint32_t bf[4];
                    uint32_t qb = (2u * c + kqB) ^ swm;
                    ldsm4(bf, kbuf + (uint32_t)(p * 16 + rB) * 512 + qb * 16);
                    mma_tf32(sf[2 * p],     af, bf[0], bf[1]);
                    mma_tf32(sf[2 * p + 1], af, bf[2], bf[3]);
                }
            }

#pragma unroll
            for (int n = 0; n < 8; n++)
#pragma unroll
                for (int j = 0; j < 4; j++) sf[n][j] *= scale;

            if (k0 + FBN - 1 > q0 + w * 16) {
#pragma unroll
                for (int n = 0; n < 8; n++) {
                    int col = k0 + n * 8 + qw * 2;
                    if (col > row0g)     sf[n][0] = -1e30f;
                    if (col + 1 > row0g) sf[n][1] = -1e30f;
                    if (col > row1g)     sf[n][2] = -1e30f;
                    if (col + 1 > row1g) sf[n][3] = -1e30f;
                }
            }

            float mx0 = -1e30f, mx1 = -1e30f;
#pragma unroll
            for (int n = 0; n < 8; n++) {
                mx0 = fmaxf(mx0, fmaxf(sf[n][0], sf[n][1]));
                mx1 = fmaxf(mx1, fmaxf(sf[n][2], sf[n][3]));
            }
            mx0 = fmaxf(mx0, __shfl_xor_sync(0xffffffffu, mx0, 1));
            mx0 = fmaxf(mx0, __shfl_xor_sync(0xffffffffu, mx0, 2));
            mx1 = fmaxf(mx1, __shfl_xor_sync(0xffffffffu, mx1, 1));
            mx1 = fmaxf(mx1, __shfl_xor_sync(0xffffffffu, mx1, 2));
            const float mn0 = fmaxf(mr0, mx0);
            const float mn1 = fmaxf(mr1, mx1);
            const float cor0 = __expf(mr0 - mn0);
            const float cor1 = __expf(mr1 - mn1);
            float rs0 = 0.0f, rs1 = 0.0f;
#pragma unroll
            for (int n = 0; n < 8; n++) {
                sf[n][0] = __expf(sf[n][0] - mn0);
                sf[n][1] = __expf(sf[n][1] - mn0);
                sf[n][2] = __expf(sf[n][2] - mn1);
                sf[n][3] = __expf(sf[n][3] - mn1);
                rs0 += sf[n][0] + sf[n][1];
                rs1 += sf[n][2] + sf[n][3];
            }
            rs0 += __shfl_xor_sync(0xffffffffu, rs0, 1);
            rs0 += __shfl_xor_sync(0xffffffffu, rs0, 2);
            rs1 += __shfl_xor_sync(0xffffffffu, rs1, 1);
            rs1 += __shfl_xor_sync(0xffffffffu, rs1, 2);
            lr0 = lr0 * cor0 + rs0;  mr0 = mn0;
            lr1 = lr1 * cor1 + rs1;  mr1 = mn1;
#pragma unroll
            for (int n = 0; n < 16; n++) {
                o_acc[n][0] *= cor0; o_acc[n][1] *= cor0;
                o_acc[n][2] *= cor1; o_acc[n][3] *= cor1;
            }

            {
                const int r0 = w * 16 + g;
                const uint32_t base0 = sb + FP_OFF + (uint32_t)r0 * 256;
                const uint32_t base1 = base0 + 8 * 256;
                const uint32_t half = (uint32_t)(qw >> 1);
                const uint32_t byte8 = (uint32_t)(qw & 1) * 8;
#pragma unroll
                for (int n = 0; n < 8; n++) {
                    uint32_t qd = ((uint32_t)(2 * n) + half) ^ (uint32_t)(g & 7);
                    sts64(base0 + qd * 16 + byte8, f2tf32(sf[n][0]), f2tf32(sf[n][1]));
                    sts64(base1 + qd * 16 + byte8, f2tf32(sf[n][2]), f2tf32(sf[n][3]));
                }
            }
        }
        __syncthreads();

        if (active) {
#pragma unroll
            for (int c = 0; c < 8; c++) {
                uint32_t af[4];
                ldsm4(af, sb + FP_OFF + (uint32_t)(w * 16 + rA) * 256
                          + ((2u * c + kqA) ^ swm) * 16);
#pragma unroll
                for (int p = 0; p < 8; p++) {
                    uint32_t bf[4];
                    ldsm4(bf, vbuf + (uint32_t)(p * 16 + rB) * 256
                              + ((2u * c + kqB) ^ swm) * 16);
                    mma_tf32(o_acc[2 * p],     af, bf[0], bf[1]);
                    mma_tf32(o_acc[2 * p + 1], af, bf[2], bf[3]);
                }
            }
        }
    }

    const float inv0 = 1.0f / lr0;
    const float inv1 = 1.0f / lr1;
#pragma unroll
    for (int n = 0; n < 16; n++) {
        const int col = h * DHEAD + n * 8 + qw * 2;
        float* p0 = out + (size_t)((size_t)b * S_LEN + row0g) * D_MODEL + col;
        float* p1 = out + (size_t)((size_t)b * S_LEN + row1g) * D_MODEL + col;
        *(uint2*)p0 = make_uint2(f2tf32(o_acc[n][0] * inv0), f2tf32(o_acc[n][1] * inv0));
        *(uint2*)p1 = make_uint2(f2tf32(o_acc[n][2] * inv1), f2tf32(o_acc[n][3] * inv1));
    }
}

// ---------------------------------------------------------------------------
extern "C" void kernel_launch(void* const* d_in, const int* in_sizes, int n_in,
                              void* d_out, int out_size) {
    const float* x     = (const float*)d_in[0];  // [B,S,D]
    const float* w_in  = (const float*)d_in[1];  // [3*H*DH, D]
    const float* w_out = (const float*)d_in[2];  // [D, H*DH]
    float* out = (float*)d_out;                  // [B,S,D]

    float *qkv, *attn, *vt, *xtf, *wintf, *wouttf;
    cudaGetSymbolAddress((void**)&qkv, g_qkv);
    cudaGetSymbolAddress((void**)&attn, g_attn);
    cudaGetSymbolAddress((void**)&vt, g_vt);
    cudaGetSymbolAddress((void**)&xtf, g_xtf);
    cudaGetSymbolAddress((void**)&wintf, g_wintf);
    cudaGetSymbolAddress((void**)&wouttf, g_wouttf);

    cudaFuncSetAttribute(gemm_mma<1>, cudaFuncAttributeMaxDynamicSharedMemorySize,
                         GEMM_SMEM);
    cudaFuncSetAttribute(gemm_mma<0>, cudaFuncAttributeMaxDynamicSharedMemorySize,
                         GEMM_SMEM);
    cudaFuncSetAttribute(flash_attn_mma, cudaFuncAttributeMaxDynamicSharedMemorySize,
                         FA_SMEM);

    // 0) tf32-round GEMM operands
    const int n4x = M_TOK * D_MODEL / 4;
    const int n4wi = E3 * D_MODEL / 4;
    const int n4wo = D_MODEL * D_MODEL / 4;
    cvt_tf32<<<(n4x + 255) / 256, 256>>>(x, xtf, n4x);
    cvt_tf32<<<(n4wi + 255) / 256, 256>>>(w_in, wintf, n4wi);
    cvt_tf32<<<(n4wo + 255) / 256, 256>>>(w_out, wouttf, n4wo);

    // 1) QKV projection (output rounded to tf32)
    dim3 g1(E3 / 128, M_TOK / 128);
    gemm_mma<1><<<g1, 128, GEMM_SMEM>>>(xtf, wintf, qkv, M_TOK, E3, D_MODEL);

    // 2) V transpose pre-pass
    dim3 gt(S_LEN / 32, DHEAD / 32, BATCH * NH);
    transpose_v<<<gt, 256>>>(qkv, vt);

    // 3) Causal flash attention (async-pipelined); output tf32-rounded
    dim3 g2(S_LEN / FBM, BATCH * NH);
    flash_attn_mma<<<g2, 256, FA_SMEM>>>(qkv, vt, attn);

    // 4) Output projection (full fp32 output)
    dim3 g3(D_MODEL / 128, M_TOK / 128);
    gemm_mma<0><<<g3, 128, GEMM_SMEM>>>(attn, wouttf, out, M_TOK, D_MODEL, D_MODEL);
}

// round 8
// speedup vs baseline: 11.8802x; 1.7616x over previous
#include <cuda_runtime.h>
#include <cuda_fp16.h>
#include <cstdint>

// Problem constants
#define BATCH   2
#define S_LEN   2048
#define D_MODEL 2048
#define NH      16
#define DHEAD   128
#define M_TOK   (BATCH * S_LEN)     // 4096 tokens
#define E3      (3 * NH * DHEAD)    // 6144 qkv features

// Scratch (alloc-free rule: __device__ globals) — fp16 pipeline
__device__ __half g_qkv[(size_t)M_TOK * E3];                // [4096, 6144]
__device__ __half g_attn[(size_t)M_TOK * D_MODEL];          // [4096, 2048]
__device__ __half g_vt[(size_t)BATCH * NH * DHEAD * S_LEN]; // [b,h,dh,s]
__device__ __half g_xh[(size_t)M_TOK * D_MODEL];            // half x
__device__ __half g_winh[(size_t)E3 * D_MODEL];             // half w_in
__device__ __half g_wouth[(size_t)D_MODEL * D_MODEL];       // half w_out

// ===========================================================================
// PTX helpers (generic sm_80+ only — toolchain targets plain compute_103)
// ===========================================================================
__device__ __forceinline__ uint32_t smem_u32(const void* p) {
    uint32_t a;
    asm("{ .reg .u64 t; cvta.to.shared.u64 t, %1; cvt.u32.u64 %0, t; }"
        : "=r"(a) : "l"(p));
    return a;
}

__device__ __forceinline__ void ldsm4(uint32_t* r, uint32_t addr) {
    asm volatile("ldmatrix.sync.aligned.m8n8.x4.shared.b16 {%0,%1,%2,%3}, [%4];"
                 : "=r"(r[0]), "=r"(r[1]), "=r"(r[2]), "=r"(r[3]) : "r"(addr));
}

// m16n8k16 fp16 MMA, fp32 accumulate
__device__ __forceinline__ void mma_f16(float* c, const uint32_t* a,
                                        uint32_t b0, uint32_t b1) {
    asm volatile(
        "mma.sync.aligned.m16n8k16.row.col.f32.f16.f16.f32 "
        "{%0,%1,%2,%3}, {%4,%5,%6,%7}, {%8,%9}, {%0,%1,%2,%3};"
        : "+f"(c[0]), "+f"(c[1]), "+f"(c[2]), "+f"(c[3])
        : "r"(a[0]), "r"(a[1]), "r"(a[2]), "r"(a[3]), "r"(b0), "r"(b1));
}

__device__ __forceinline__ void sts32(uint32_t addr, uint32_t x) {
    asm volatile("st.shared.b32 [%0], %1;" :: "r"(addr), "r"(x));
}

__device__ __forceinline__ uint32_t packh2(float a, float b) {
    __half2 h = __floats2half2_rn(a, b);
    return *(const uint32_t*)&h;
}

__device__ __forceinline__ void cp16(uint32_t dst, const void* src) {
    asm volatile("cp.async.cg.shared.global [%0], [%1], 16;"
                 :: "r"(dst), "l"(src));
}
#define CP_COMMIT() asm volatile("cp.async.commit_group;" ::: "memory")
#define CP_WAIT1()  asm volatile("cp.async.wait_group 1;" ::: "memory")
#define CP_WAIT0()  asm volatile("cp.async.wait_group 0;" ::: "memory")

// ===========================================================================
// fp32 -> fp16 conversion pre-pass
// ===========================================================================
__global__ __launch_bounds__(256)
void cvt_half(const float* __restrict__ src, __half* __restrict__ dst, int n4) {
    int i = blockIdx.x * 256 + threadIdx.x;
    if (i < n4) {
        float4 v = ((const float4*)src)[i];
        __half2 h0 = __floats2half2_rn(v.x, v.y);
        __half2 h1 = __floats2half2_rn(v.z, v.w);
        uint2 o;
        o.x = *(const uint32_t*)&h0;
        o.y = *(const uint32_t*)&h1;
        ((uint2*)dst)[i] = o;
    }
}

// ===========================================================================
// cp.async 3-stage fp16 GEMM: C[M,N] = A[M,K] * B[N,K]^T
// CTA tile 128x128, 128 threads (4 warps), warp tile 64x64.
// K-chunk 64 halves (128B/row, 8 quads, quad-xor swizzle).
// Per k16-step: 8 LDSM.x4 per 32 MMA (each MMA = k16, 2x the tf32 work).
// Smem 3 x 32KB = 96KB -> 2 CTAs/SM.
// OUT_HALF=1: C is __half*; else float*.
// ===========================================================================
#define NSTAGE 3
#define STAGE_B 32768
#define GEMM_SMEM (NSTAGE * STAGE_B)

template <int OUT_HALF>
__global__ __launch_bounds__(128, 2)
void gemm_mma(const __half* __restrict__ A, const __half* __restrict__ B,
              void* __restrict__ Cv, int M, int N, int K) {
    extern __shared__ unsigned char dsm[];
    const uint32_t sbase = smem_u32(dsm);

    const int tid  = threadIdx.x;
    const int lane = tid & 31;
    const int wid  = tid >> 5;      // 0..3
    const int wm   = wid & 1;       // m band (64 rows)
    const int wn   = wid >> 1;      // n band (64 cols)
    const int bm   = blockIdx.y * 128;
    const int bn   = blockIdx.x * 128;

    // cp.async staging: thread -> (row lrow + it*16, quad lq of 8 halves)
    const int lrow = tid >> 3;      // 0..15
    const int lq   = tid & 7;       // 0..7
    const __half* Ag = A + (size_t)(bm + lrow) * K + lq * 8;
    const __half* Bg = B + (size_t)(bn + lrow) * K + lq * 8;
    const uint32_t sq = (uint32_t)((lq ^ (lrow & 7)) * 16);
    const uint32_t stsA = sbase + (uint32_t)lrow * 128 + sq;
    const uint32_t stsB = stsA + 16384;

    // ldmatrix per-lane indices (quad = 16B = 8 halves; k16-step = 2 quads)
    const int tA = lane >> 3;
    const int mA = wm * 64 + ((tA & 1) << 3) + (lane & 7);     // +16*t
    const uint32_t kqA = (uint32_t)(tA >> 1);
    const int nB = wn * 64 + ((lane >> 4) << 3) + (lane & 7);  // +16*p
    const uint32_t kqB = (uint32_t)((lane >> 3) & 1);
    const uint32_t swm = (uint32_t)(lane & 7);

    float cacc[4][8][4];
#pragma unroll
    for (int t = 0; t < 4; t++)
#pragma unroll
        for (int n = 0; n < 8; n++)
#pragma unroll
            for (int j = 0; j < 4; j++) cacc[t][n][j] = 0.0f;

    const int NC = K >> 6;   // chunks of 64 halves

#pragma unroll
    for (int s = 0; s < NSTAGE - 1; s++) {
        const uint32_t so = (uint32_t)s * STAGE_B;
        const int k0 = s * 64;
#pragma unroll
        for (int it = 0; it < 8; it++) {
            cp16(stsA + so + it * 16 * 128u, Ag + k0 + (size_t)it * 16 * K);
            cp16(stsB + so + it * 16 * 128u, Bg + k0 + (size_t)it * 16 * K);
        }
        CP_COMMIT();
    }

    for (int ch = 0; ch < NC; ch++) {
        CP_WAIT1();
        __syncthreads();

        if (ch + NSTAGE - 1 < NC) {
            const uint32_t so = (uint32_t)((ch + NSTAGE - 1) % NSTAGE) * STAGE_B;
            const int k0 = (ch + NSTAGE - 1) * 64;
#pragma unroll
            for (int it = 0; it < 8; it++) {
                cp16(stsA + so + it * 16 * 128u, Ag + k0 + (size_t)it * 16 * K);
                cp16(stsB + so + it * 16 * 128u, Bg + k0 + (size_t)it * 16 * K);
            }
        }
        CP_COMMIT();

        const uint32_t aBase = sbase + (uint32_t)(ch % NSTAGE) * STAGE_B;
        const uint32_t bBase = aBase + 16384;
#pragma unroll
        for (int c = 0; c < 4; c++) {    // 4 k16-steps per 64-half chunk
            uint32_t afr[4][4];
#pragma unroll
            for (int t = 0; t < 4; t++) {
                uint32_t q = (2u * c + kqA) ^ swm;
                ldsm4(afr[t], aBase + (uint32_t)(mA + 16 * t) * 128 + q * 16);
            }
            uint32_t bfr[4][4];
#pragma unroll
            for (int p = 0; p < 4; p++) {
                uint32_t q = (2u * c + kqB) ^ swm;
                ldsm4(bfr[p], bBase + (uint32_t)(nB + 16 * p) * 128 + q * 16);
            }
#pragma unroll
            for (int t = 0; t < 4; t++)
#pragma unroll
                for (int p = 0; p < 4; p++) {
                    mma_f16(cacc[t][2 * p],     afr[t], bfr[p][0], bfr[p][1]);
                    mma_f16(cacc[t][2 * p + 1], afr[t], bfr[p][2], bfr[p][3]);
                }
        }
    }
    CP_WAIT0();

    const int g = lane >> 2;
    const int w2 = (lane & 3) * 2;
#pragma unroll
    for (int t = 0; t < 4; t++) {
        const int row0 = bm + wm * 64 + t * 16 + g;
        const int col0 = bn + wn * 64 + w2;
#pragma unroll
        for (int n = 0; n < 8; n++) {
            if (OUT_HALF) {
                __half* C = (__half*)Cv;
                *(uint32_t*)(C + (size_t)row0 * N + col0 + n * 8) =
                    packh2(cacc[t][n][0], cacc[t][n][1]);
                *(uint32_t*)(C + (size_t)(row0 + 8) * N + col0 + n * 8) =
                    packh2(cacc[t][n][2], cacc[t][n][3]);
            } else {
                float* C = (float*)Cv;
                *(float2*)(C + (size_t)row0 * N + col0 + n * 8) =
                    make_float2(cacc[t][n][0], cacc[t][n][1]);
                *(float2*)(C + (size_t)(row0 + 8) * N + col0 + n * 8) =
                    make_float2(cacc[t][n][2], cacc[t][n][3]);
            }
        }
    }
}

// ===========================================================================
// V transpose pre-pass: g_qkv V-slices (half) -> g_vt[b,h,dh,s] (half)
// ===========================================================================
__global__ __launch_bounds__(256)
void transpose_v(const __half* __restrict__ qkv, __half* __restrict__ vt) {
    __shared__ __half t[32][33];
    const int bh = blockIdx.z;
    const int b = bh >> 4, h = bh & 15;
    const int s0 = blockIdx.x * 32;
    const int d0 = blockIdx.y * 32;
    const int tx = threadIdx.x & 31;
    const int ty = threadIdx.x >> 5;

    const __half* src = qkv + (size_t)b * S_LEN * E3 + (size_t)h * 384 + 256;
#pragma unroll
    for (int i = ty; i < 32; i += 8)
        t[i][tx] = src[(size_t)(s0 + i) * E3 + d0 + tx];
    __syncthreads();
    __half* dst = vt + ((size_t)bh * DHEAD + d0) * S_LEN + s0;
#pragma unroll
    for (int i = ty; i < 32; i += 8)
        dst[(size_t)i * S_LEN + tx] = t[tx][i];
}

// ===========================================================================
// Flash attention, mma.sync fp16, cp.async-pipelined. Causal.
// CTA: 128 q-rows; 8 warps (warp w = m16 band); kv tiles 64, K/Vt double-buf.
// Smem (quad-xor swizzled, quad = 16B = 8 halves):
//   Q  128x256B @ 0       (32768)
//   K0  64x256B @ 32768   K1 @ 49152     (16384 each)
//   V0 128x128B @ 65536   V1 @ 81920     (16384 each)
//   P  128x128B @ 98304                  (16384)
// Total 114688. Block order reversed so heavy (large-q0) CTAs launch first.
// ===========================================================================
#define FBM 128
#define FBN 64
#define FQ_OFF 0u
#define FK_OFF 32768u
#define FV_OFF 65536u
#define FP_OFF 98304u
#define FA_SMEM 114688

__global__ __launch_bounds__(256, 1)
void flash_attn_mma(const __half* __restrict__ qkv, const __half* __restrict__ vt,
                    __half* __restrict__ out) {
    extern __shared__ unsigned char fsm[];
    const uint32_t sb = smem_u32(fsm);
    const int tid = threadIdx.x;
    const int lane = tid & 31;
    const int w = tid >> 5;
    const int bh = blockIdx.y;
    const int b = bh >> 4, h = bh & 15;
    const int q0 = ((int)gridDim.x - 1 - (int)blockIdx.x) * FBM;  // heavy first

    const float scale = 0.08838834764831845f;  // 1/sqrt(128)
    const size_t qbase = (size_t)b * S_LEN * E3 + (size_t)h * 384;
    const __half* vsrc0 = vt + (size_t)bh * DHEAD * S_LEN;

    // Prologue: Q (128x16 quads) + K(0) (64x16) + Vt(0) (128x8)
#pragma unroll
    for (int it = 0; it < 8; it++) {
        int idx = tid + it * 256;
        int r = idx >> 4, kq = idx & 15;
        cp16(sb + FQ_OFF + (uint32_t)r * 256 + (uint32_t)((kq ^ (r & 7)) * 16),
             qkv + qbase + (size_t)(q0 + r) * E3 + kq * 8);
    }
#pragma unroll
    for (int it = 0; it < 4; it++) {
        int idx = tid + it * 256;
        int r = idx >> 4, kq = idx & 15;
        cp16(sb + FK_OFF + (uint32_t)r * 256 + (uint32_t)((kq ^ (r & 7)) * 16),
             qkv + qbase + (size_t)r * E3 + 128 + kq * 8);
    }
#pragma unroll
    for (int it = 0; it < 4; it++) {
        int idx = tid + it * 256;
        int dh = idx >> 3, kq = idx & 7;
        cp16(sb + FV_OFF + (uint32_t)dh * 128 + (uint32_t)((kq ^ (dh & 7)) * 16),
             vsrc0 + (size_t)dh * S_LEN + kq * 8);
    }
    CP_COMMIT();

    const int tA = lane >> 3;
    const int rA = ((tA & 1) << 3) + (lane & 7);
    const uint32_t kqA = (uint32_t)(tA >> 1);
    const int rB = ((lane >> 4) << 3) + (lane & 7);
    const uint32_t kqB = (uint32_t)((lane >> 3) & 1);
    const uint32_t swm = (uint32_t)(lane & 7);
    const int g = lane >> 2;
    const int qw = lane & 3;

    float o_acc[16][4];
#pragma unroll
    for (int n = 0; n < 16; n++)
#pragma unroll
        for (int j = 0; j < 4; j++) o_acc[n][j] = 0.0f;
    float mr0 = -1e30f, mr1 = -1e30f, lr0 = 0.0f, lr1 = 0.0f;

    const int row0g = q0 + w * 16 + g;
    const int row1g = row0g + 8;

    const int nkt = q0 / FBN + 2;
    for (int kb = 0; kb < nkt; kb++) {
        const int k0 = kb * FBN;
        const uint32_t kbuf = sb + FK_OFF + (uint32_t)(kb & 1) * 16384u;
        const uint32_t vbuf = sb + FV_OFF + (uint32_t)(kb & 1) * 16384u;

        CP_WAIT0();
        __syncthreads();

        if (kb + 1 < nkt) {
            const int kn = k0 + FBN;
            const uint32_t kbufn = sb + FK_OFF + (uint32_t)((kb + 1) & 1) * 16384u;
            const uint32_t vbufn = sb + FV_OFF + (uint32_t)((kb + 1) & 1) * 16384u;
#pragma unroll
            for (int it = 0; it < 4; it++) {
                int idx = tid + it * 256;
                int r = idx >> 4, kq = idx & 15;
                cp16(kbufn + (uint32_t)r * 256 + (uint32_t)((kq ^ (r & 7)) * 16),
                     qkv + qbase + (size_t)(kn + r) * E3 + 128 + kq * 8);
            }
#pragma unroll
            for (int it = 0; it < 4; it++) {
                int idx = tid + it * 256;
                int dh = idx >> 3, kq = idx & 7;
                cp16(vbufn + (uint32_t)dh * 128 + (uint32_t)((kq ^ (dh & 7)) * 16),
                     vsrc0 + (size_t)dh * S_LEN + kn + kq * 8);
            }
        }
        CP_COMMIT();

        const bool active = (k0 <= q0 + w * 16 + 15);
        if (active) {
            // S = Q * K^T : m16 x n64 x k128 (8 k16-steps)
            float sf[8][4];
#pragma unroll
            for (int n = 0; n < 8; n++)
#pragma unroll
                for (int j = 0; j < 4; j++) sf[n][j] = 0.0f;

#pragma unroll
            for (int c = 0; c < 8; c++) {
                uint32_t af[4];
                uint32_t qa = (2u * c + kqA) ^ swm;   // 4-bit quad; xor low 3
                ldsm4(af, sb + FQ_OFF + (uint32_t)(w * 16 + rA) * 256 + qa * 16);
#pragma unroll
                for (int p = 0; p < 4; p++) {
                    uint32_t bf[4];
                    uint32_t qb = (2u * c + kqB) ^ swm;
                    ldsm4(bf, kbuf + (uint32_t)(p * 16 + rB) * 256 + qb * 16);
                    mma_f16(sf[2 * p],     af, bf[0], bf[1]);
                    mma_f16(sf[2 * p + 1], af, bf[2], bf[3]);
                }
            }

#pragma unroll
            for (int n = 0; n < 8; n++)
#pragma unroll
                for (int j = 0; j < 4; j++) sf[n][j] *= scale;

            if (k0 + FBN - 1 > q0 + w * 16) {
#pragma unroll
                for (int n = 0; n < 8; n++) {
                    int col = k0 + n * 8 + qw * 2;
                    if (col > row0g)     sf[n][0] = -1e30f;
                    if (col + 1 > row0g) sf[n][1] = -1e30f;
                    if (col > row1g)     sf[n][2] = -1e30f;
                    if (col + 1 > row1g) sf[n][3] = -1e30f;
                }
            }

            float mx0 = -1e30f, mx1 = -1e30f;
#pragma unroll
            for (int n = 0; n < 8; n++) {
                mx0 = fmaxf(mx0, fmaxf(sf[n][0], sf[n][1]));
                mx1 = fmaxf(mx1, fmaxf(sf[n][2], sf[n][3]));
            }
            mx0 = fmaxf(mx0, __shfl_xor_sync(0xffffffffu, mx0, 1));
            mx0 = fmaxf(mx0, __shfl_xor_sync(0xffffffffu, mx0, 2));
            mx1 = fmaxf(mx1, __shfl_xor_sync(0xffffffffu, mx1, 1));
            mx1 = fmaxf(mx1, __shfl_xor_sync(0xffffffffu, mx1, 2));
            const float mn0 = fmaxf(mr0, mx0);
            const float mn1 = fmaxf(mr1, mx1);
            const float cor0 = __expf(mr0 - mn0);
            const float cor1 = __expf(mr1 - mn1);
            float rs0 = 0.0f, rs1 = 0.0f;
#pragma unroll
            for (int n = 0; n < 8; n++) {
                sf[n][0] = __expf(sf[n][0] - mn0);
                sf[n][1] = __expf(sf[n][1] - mn0);
                sf[n][2] = __expf(sf[n][2] - mn1);
                sf[n][3] = __expf(sf[n][3] - mn1);
                rs0 += sf[n][0] + sf[n][1];
                rs1 += sf[n][2] + sf[n][3];
            }
            rs0 += __shfl_xor_sync(0xffffffffu, rs0, 1);
            rs0 += __shfl_xor_sync(0xffffffffu, rs0, 2);
            rs1 += __shfl_xor_sync(0xffffffffu, rs1, 1);
            rs1 += __shfl_xor_sync(0xffffffffu, rs1, 2);
            lr0 = lr0 * cor0 + rs0;  mr0 = mn0;
            lr1 = lr1 * cor1 + rs1;  mr1 = mn1;
#pragma unroll
            for (int n = 0; n < 16; n++) {
                o_acc[n][0] *= cor0; o_acc[n][1] *= cor0;
                o_acc[n][2] *= cor1; o_acc[n][3] *= cor1;
            }

            // Write P (half) swizzled: row r, 8 quads; element pair at
            // quad n, byte (qw*4) -> swizzled quad n ^ (r&7)
            {
                const int r0 = w * 16 + g;
                const uint32_t base0 = sb + FP_OFF + (uint32_t)r0 * 128;
                const uint32_t base1 = base0 + 8 * 128;
                const uint32_t b4 = (uint32_t)qw * 4;
#pragma unroll
                for (int n = 0; n < 8; n++) {
                    uint32_t qd = (uint32_t)n ^ (uint32_t)(g & 7);
                    sts32(base0 + qd * 16 + b4, packh2(sf[n][0], sf[n][1]));
                    sts32(base1 + qd * 16 + b4, packh2(sf[n][2], sf[n][3]));
                }
            }
        }
        __syncthreads();

        if (active) {
            // O += P * Vt^T : m16 x n128 x k64 (4 k16-steps)
#pragma unroll
            for (int c = 0; c < 4; c++) {
                uint32_t af[4];
                ldsm4(af, sb + FP_OFF + (uint32_t)(w * 16 + rA) * 128
                          + ((2u * c + kqA) ^ swm) * 16);
#pragma unroll
                for (int p = 0; p < 8; p++) {
                    uint32_t bf[4];
                    ldsm4(bf, vbuf + (uint32_t)(p * 16 + rB) * 128
                              + ((2u * c + kqB) ^ swm) * 16);
                    mma_f16(o_acc[2 * p],     af, bf[0], bf[1]);
                    mma_f16(o_acc[2 * p + 1], af, bf[2], bf[3]);
                }
            }
        }
    }

    // Epilogue: normalize + write half (GEMM2 consumes directly)
    const float inv0 = 1.0f / lr0;
    const float inv1 = 1.0f / lr1;
#pragma unroll
    for (int n = 0; n < 16; n++) {
        const int col = h * DHEAD + n * 8 + qw * 2;
        __half* p0 = out + (size_t)((size_t)b * S_LEN + row0g) * D_MODEL + col;
        __half* p1 = out + (size_t)((size_t)b * S_LEN + row1g) * D_MODEL + col;
        *(uint32_t*)p0 = packh2(o_acc[n][0] * inv0, o_acc[n][1] * inv0);
        *(uint32_t*)p1 = packh2(o_acc[n][2] * inv1, o_acc[n][3] * inv1);
    }
}

// ---------------------------------------------------------------------------
extern "C" void kernel_launch(void* const* d_in, const int* in_sizes, int n_in,
                              void* d_out, int out_size) {
    const float* x     = (const float*)d_in[0];  // [B,S,D]
    const float* w_in  = (const float*)d_in[1];  // [3*H*DH, D]
    const float* w_out = (const float*)d_in[2];  // [D, H*DH]
    float* out = (float*)d_out;                  // [B,S,D]

    __half *qkv, *attn, *vt, *xh, *winh, *wouth;
    cudaGetSymbolAddress((void**)&qkv, g_qkv);
    cudaGetSymbolAddress((void**)&attn, g_attn);
    cudaGetSymbolAddress((void**)&vt, g_vt);
    cudaGetSymbolAddress((void**)&xh, g_xh);
    cudaGetSymbolAddress((void**)&winh, g_winh);
    cudaGetSymbolAddress((void**)&wouth, g_wouth);

    cudaFuncSetAttribute(gemm_mma<1>, cudaFuncAttributeMaxDynamicSharedMemorySize,
                         GEMM_SMEM);
    cudaFuncSetAttribute(gemm_mma<0>, cudaFuncAttributeMaxDynamicSharedMemorySize,
                         GEMM_SMEM);
    cudaFuncSetAttribute(flash_attn_mma, cudaFuncAttributeMaxDynamicSharedMemorySize,
                         FA_SMEM);

    // 0) fp16-convert GEMM operands
    const int n4x = M_TOK * D_MODEL / 4;
    const int n4wi = E3 * D_MODEL / 4;
    const int n4wo = D_MODEL * D_MODEL / 4;
    cvt_half<<<(n4x + 255) / 256, 256>>>(x, xh, n4x);
    cvt_half<<<(n4wi + 255) / 256, 256>>>(w_in, winh, n4wi);
    cvt_half<<<(n4wo + 255) / 256, 256>>>(w_out, wouth, n4wo);

    // 1) QKV projection (half output)
    dim3 g1(E3 / 128, M_TOK / 128);
    gemm_mma<1><<<g1, 128, GEMM_SMEM>>>(xh, winh, qkv, M_TOK, E3, D_MODEL);

    // 2) V transpose pre-pass
    dim3 gt(S_LEN / 32, DHEAD / 32, BATCH * NH);
    transpose_v<<<gt, 256>>>(qkv, vt);

    // 3) Causal flash attention (async-pipelined); half output
    dim3 g2(S_LEN / FBM, BATCH * NH);
    flash_attn_mma<<<g2, 256, FA_SMEM>>>(qkv, vt, attn);

    // 4) Output projection (fp32 output)
    dim3 g3(D_MODEL / 128, M_TOK / 128);
    gemm_mma<0><<<g3, 128, GEMM_SMEM>>>(attn, wouth, out, M_TOK, D_MODEL, D_MODEL);
}

// round 9
// speedup vs baseline: 12.9362x; 1.0889x over previous
#include <cuda_runtime.h>
#include <cuda_fp16.h>
#include <cstdint>

// Problem constants
#define BATCH   2
#define S_LEN   2048
#define D_MODEL 2048
#define NH      16
#define DHEAD   128
#define M_TOK   (BATCH * S_LEN)     // 4096 tokens
#define E3      (3 * NH * DHEAD)    // 6144 qkv features

// Scratch (alloc-free rule: __device__ globals) — fp16 pipeline
__device__ __half g_qkv[(size_t)M_TOK * E3];       // [4096, 6144]
__device__ __half g_attn[(size_t)M_TOK * D_MODEL]; // [4096, 2048]
__device__ __half g_xh[(size_t)M_TOK * D_MODEL];   // half x
__device__ __half g_winh[(size_t)E3 * D_MODEL];    // half w_in
__device__ __half g_wouth[(size_t)D_MODEL * D_MODEL]; // half w_out

// ===========================================================================
// PTX helpers (generic sm_80+ only — toolchain targets plain compute_103)
// ===========================================================================
__device__ __forceinline__ uint32_t smem_u32(const void* p) {
    uint32_t a;
    asm("{ .reg .u64 t; cvta.to.shared.u64 t, %1; cvt.u32.u64 %0, t; }"
        : "=r"(a) : "l"(p));
    return a;
}

__device__ __forceinline__ void ldsm4(uint32_t* r, uint32_t addr) {
    asm volatile("ldmatrix.sync.aligned.m8n8.x4.shared.b16 {%0,%1,%2,%3}, [%4];"
                 : "=r"(r[0]), "=r"(r[1]), "=r"(r[2]), "=r"(r[3]) : "r"(addr));
}

__device__ __forceinline__ void ldsm4t(uint32_t* r, uint32_t addr) {
    asm volatile("ldmatrix.sync.aligned.m8n8.x4.trans.shared.b16 {%0,%1,%2,%3}, [%4];"
                 : "=r"(r[0]), "=r"(r[1]), "=r"(r[2]), "=r"(r[3]) : "r"(addr));
}

// m16n8k16 fp16 MMA, fp32 accumulate
__device__ __forceinline__ void mma_f16(float* c, const uint32_t* a,
                                        uint32_t b0, uint32_t b1) {
    asm volatile(
        "mma.sync.aligned.m16n8k16.row.col.f32.f16.f16.f32 "
        "{%0,%1,%2,%3}, {%4,%5,%6,%7}, {%8,%9}, {%0,%1,%2,%3};"
        : "+f"(c[0]), "+f"(c[1]), "+f"(c[2]), "+f"(c[3])
        : "r"(a[0]), "r"(a[1]), "r"(a[2]), "r"(a[3]), "r"(b0), "r"(b1));
}

__device__ __forceinline__ uint32_t packh2(float a, float b) {
    __half2 h = __floats2half2_rn(a, b);
    return *(const uint32_t*)&h;
}

__device__ __forceinline__ void cp16(uint32_t dst, const void* src) {
    asm volatile("cp.async.cg.shared.global [%0], [%1], 16;"
                 :: "r"(dst), "l"(src));
}
#define CP_COMMIT() asm volatile("cp.async.commit_group;" ::: "memory")
#define CP_WAIT1()  asm volatile("cp.async.wait_group 1;" ::: "memory")
#define CP_WAIT0()  asm volatile("cp.async.wait_group 0;" ::: "memory")

// ===========================================================================
// Fused fp32 -> fp16 conversion (x, w_in, w_out in one launch)
// ===========================================================================
__global__ __launch_bounds__(256)
void cvt_half3(const float* __restrict__ x,  __half* __restrict__ xh,  int n4x,
               const float* __restrict__ wi, __half* __restrict__ wih, int n4wi,
               const float* __restrict__ wo, __half* __restrict__ woh, int n4wo) {
    int i = blockIdx.x * 256 + threadIdx.x;
    const float* s;
    __half* d;
    int k;
    if (i < n4x)                  { s = x;  d = xh;  k = i; }
    else if (i < n4x + n4wi)      { s = wi; d = wih; k = i - n4x; }
    else if (i < n4x + n4wi + n4wo) { s = wo; d = woh; k = i - n4x - n4wi; }
    else return;
    float4 v = ((const float4*)s)[k];
    __half2 h0 = __floats2half2_rn(v.x, v.y);
    __half2 h1 = __floats2half2_rn(v.z, v.w);
    uint2 o;
    o.x = *(const uint32_t*)&h0;
    o.y = *(const uint32_t*)&h1;
    ((uint2*)d)[k] = o;
}

// ===========================================================================
// cp.async 3-stage fp16 GEMM (R8 WIN — unchanged): C[M,N] = A[M,K]*B[N,K]^T
// ===========================================================================
#define NSTAGE 3
#define STAGE_B 32768
#define GEMM_SMEM (NSTAGE * STAGE_B)

template <int OUT_HALF>
__global__ __launch_bounds__(128, 2)
void gemm_mma(const __half* __restrict__ A, const __half* __restrict__ B,
              void* __restrict__ Cv, int M, int N, int K) {
    extern __shared__ unsigned char dsm[];
    const uint32_t sbase = smem_u32(dsm);

    const int tid  = threadIdx.x;
    const int lane = tid & 31;
    const int wid  = tid >> 5;
    const int wm   = wid & 1;
    const int wn   = wid >> 1;
    const int bm   = blockIdx.y * 128;
    const int bn   = blockIdx.x * 128;

    const int lrow = tid >> 3;
    const int lq   = tid & 7;
    const __half* Ag = A + (size_t)(bm + lrow) * K + lq * 8;
    const __half* Bg = B + (size_t)(bn + lrow) * K + lq * 8;
    const uint32_t sq = (uint32_t)((lq ^ (lrow & 7)) * 16);
    const uint32_t stsA = sbase + (uint32_t)lrow * 128 + sq;
    const uint32_t stsB = stsA + 16384;

    const int tA = lane >> 3;
    const int mA = wm * 64 + ((tA & 1) << 3) + (lane & 7);
    const uint32_t kqA = (uint32_t)(tA >> 1);
    const int nB = wn * 64 + ((lane >> 4) << 3) + (lane & 7);
    const uint32_t kqB = (uint32_t)((lane >> 3) & 1);
    const uint32_t swm = (uint32_t)(lane & 7);

    float cacc[4][8][4];
#pragma unroll
    for (int t = 0; t < 4; t++)
#pragma unroll
        for (int n = 0; n < 8; n++)
#pragma unroll
            for (int j = 0; j < 4; j++) cacc[t][n][j] = 0.0f;

    const int NC = K >> 6;

#pragma unroll
    for (int s = 0; s < NSTAGE - 1; s++) {
        const uint32_t so = (uint32_t)s * STAGE_B;
        const int k0 = s * 64;
#pragma unroll
        for (int it = 0; it < 8; it++) {
            cp16(stsA + so + it * 16 * 128u, Ag + k0 + (size_t)it * 16 * K);
            cp16(stsB + so + it * 16 * 128u, Bg + k0 + (size_t)it * 16 * K);
        }
        CP_COMMIT();
    }

    for (int ch = 0; ch < NC; ch++) {
        CP_WAIT1();
        __syncthreads();

        if (ch + NSTAGE - 1 < NC) {
            const uint32_t so = (uint32_t)((ch + NSTAGE - 1) % NSTAGE) * STAGE_B;
            const int k0 = (ch + NSTAGE - 1) * 64;
#pragma unroll
            for (int it = 0; it < 8; it++) {
                cp16(stsA + so + it * 16 * 128u, Ag + k0 + (size_t)it * 16 * K);
                cp16(stsB + so + it * 16 * 128u, Bg + k0 + (size_t)it * 16 * K);
            }
        }
        CP_COMMIT();

        const uint32_t aBase = sbase + (uint32_t)(ch % NSTAGE) * STAGE_B;
        const uint32_t bBase = aBase + 16384;
#pragma unroll
        for (int c = 0; c < 4; c++) {
            uint32_t afr[4][4];
#pragma unroll
            for (int t = 0; t < 4; t++) {
                uint32_t q = (2u * c + kqA) ^ swm;
                ldsm4(afr[t], aBase + (uint32_t)(mA + 16 * t) * 128 + q * 16);
            }
            uint32_t bfr[4][4];
#pragma unroll
            for (int p = 0; p < 4; p++) {
                uint32_t q = (2u * c + kqB) ^ swm;
                ldsm4(bfr[p], bBase + (uint32_t)(nB + 16 * p) * 128 + q * 16);
            }
#pragma unroll
            for (int t = 0; t < 4; t++)
#pragma unroll
                for (int p = 0; p < 4; p++) {
                    mma_f16(cacc[t][2 * p],     afr[t], bfr[p][0], bfr[p][1]);
                    mma_f16(cacc[t][2 * p + 1], afr[t], bfr[p][2], bfr[p][3]);
                }
        }
    }
    CP_WAIT0();

    const int g = lane >> 2;
    const int w2 = (lane & 3) * 2;
#pragma unroll
    for (int t = 0; t < 4; t++) {
        const int row0 = bm + wm * 64 + t * 16 + g;
        const int col0 = bn + wn * 64 + w2;
#pragma unroll
        for (int n = 0; n < 8; n++) {
            if (OUT_HALF) {
                __half* C = (__half*)Cv;
                *(uint32_t*)(C + (size_t)row0 * N + col0 + n * 8) =
                    packh2(cacc[t][n][0], cacc[t][n][1]);
                *(uint32_t*)(C + (size_t)(row0 + 8) * N + col0 + n * 8) =
                    packh2(cacc[t][n][2], cacc[t][n][3]);
            } else {
                float* C = (float*)Cv;
                *(float2*)(C + (size_t)row0 * N + col0 + n * 8) =
                    make_float2(cacc[t][n][0], cacc[t][n][1]);
                *(float2*)(C + (size_t)(row0 + 8) * N + col0 + n * 8) =
                    make_float2(cacc[t][n][2], cacc[t][n][3]);
            }
        }
    }
}

// ===========================================================================
// Flash attention v3: fp16 mma, register-resident P, trans-ldmatrix V.
// CTA: 128 q-rows; 8 warps (warp w = m16 band); kv tiles 64, K/V double-buf.
// V consumed directly from qkv (row-major [s][dh]) via ldmatrix.trans —
// no transpose pre-pass, no Vt buffer, no P smem, ONE barrier per tile.
// Smem (quad-xor swizzled):
//   Q  128x256B @ 0       (32768)
//   K0  64x256B @ 32768   K1 @ 49152   (16384 each)
//   V0  64x256B @ 65536   V1 @ 81920   (16384 each)
// Total 98304.
// ===========================================================================
#define FBM 128
#define FBN 64
#define FQ_OFF 0u
#define FK_OFF 32768u
#define FV_OFF 65536u
#define FA_SMEM 98304

__global__ __launch_bounds__(256, 1)
void flash_attn_mma(const __half* __restrict__ qkv, __half* __restrict__ out) {
    extern __shared__ unsigned char fsm[];
    const uint32_t sb = smem_u32(fsm);
    const int tid = threadIdx.x;
    const int lane = tid & 31;
    const int w = tid >> 5;
    const int bh = blockIdx.y;
    const int b = bh >> 4, h = bh & 15;
    const int q0 = ((int)gridDim.x - 1 - (int)blockIdx.x) * FBM;  // heavy first

    const float scale = 0.08838834764831845f;  // 1/sqrt(128)
    const size_t qbase = (size_t)b * S_LEN * E3 + (size_t)h * 384;

    // Prologue: Q (128x16 quads) + K(0) (64x16) + V(0) (64x16)
#pragma unroll
    for (int it = 0; it < 8; it++) {
        int idx = tid + it * 256;
        int r = idx >> 4, kq = idx & 15;
        cp16(sb + FQ_OFF + (uint32_t)r * 256 + (uint32_t)((kq ^ (r & 7)) * 16),
             qkv + qbase + (size_t)(q0 + r) * E3 + kq * 8);
    }
#pragma unroll
    for (int it = 0; it < 4; it++) {
        int idx = tid + it * 256;
        int r = idx >> 4, kq = idx & 15;
        cp16(sb + FK_OFF + (uint32_t)r * 256 + (uint32_t)((kq ^ (r & 7)) * 16),
             qkv + qbase + (size_t)r * E3 + 128 + kq * 8);
    }
#pragma unroll
    for (int it = 0; it < 4; it++) {
        int idx = tid + it * 256;
        int r = idx >> 4, kq = idx & 15;
        cp16(sb + FV_OFF + (uint32_t)r * 256 + (uint32_t)((kq ^ (r & 7)) * 16),
             qkv + qbase + (size_t)r * E3 + 256 + kq * 8);
    }
    CP_COMMIT();

    // ldmatrix per-lane indices
    const int tA = lane >> 3;
    const int rA = ((tA & 1) << 3) + (lane & 7);
    const uint32_t kqA = (uint32_t)(tA >> 1);
    const int rB = ((lane >> 4) << 3) + (lane & 7);
    const uint32_t kqB = (uint32_t)((lane >> 3) & 1);
    const uint32_t swm = (uint32_t)(lane & 7);
    // trans-ldmatrix (V) per-lane: source row within k16 block, dh-quad select
    const int rV  = ((lane >> 3) & 1) * 8 + (lane & 7);
    const int nqV = lane >> 4;
    const int g = lane >> 2;
    const int qw = lane & 3;

    float o_acc[16][4];
#pragma unroll
    for (int n = 0; n < 16; n++)
#pragma unroll
        for (int j = 0; j < 4; j++) o_acc[n][j] = 0.0f;
    float mr0 = -1e30f, mr1 = -1e30f, lr0 = 0.0f, lr1 = 0.0f;

    const int row0g = q0 + w * 16 + g;
    const int row1g = row0g + 8;

    const int nkt = q0 / FBN + 2;
    for (int kb = 0; kb < nkt; kb++) {
        const int k0 = kb * FBN;
        const uint32_t kbuf = sb + FK_OFF + (uint32_t)(kb & 1) * 16384u;
        const uint32_t vbuf = sb + FV_OFF + (uint32_t)(kb & 1) * 16384u;

        CP_WAIT0();
        __syncthreads();   // cp.async data visible; prev tile fully consumed

        if (kb + 1 < nkt) {
            const int kn = k0 + FBN;
            const uint32_t kbufn = sb + FK_OFF + (uint32_t)((kb + 1) & 1) * 16384u;
            const uint32_t vbufn = sb + FV_OFF + (uint32_t)((kb + 1) & 1) * 16384u;
#pragma unroll
            for (int it = 0; it < 4; it++) {
                int idx = tid + it * 256;
                int r = idx >> 4, kq = idx & 15;
                cp16(kbufn + (uint32_t)r * 256 + (uint32_t)((kq ^ (r & 7)) * 16),
                     qkv + qbase + (size_t)(kn + r) * E3 + 128 + kq * 8);
            }
#pragma unroll
            for (int it = 0; it < 4; it++) {
                int idx = tid + it * 256;
                int r = idx >> 4, kq = idx & 15;
                cp16(vbufn + (uint32_t)r * 256 + (uint32_t)((kq ^ (r & 7)) * 16),
                     qkv + qbase + (size_t)(kn + r) * E3 + 256 + kq * 8);
            }
        }
        CP_COMMIT();

        const bool active = (k0 <= q0 + w * 16 + 15);
        if (active) {
            // S = Q * K^T : m16 x n64 x k128 (8 k16-steps)
            float sf[8][4];
#pragma unroll
            for (int n = 0; n < 8; n++)
#pragma unroll
                for (int j = 0; j < 4; j++) sf[n][j] = 0.0f;

#pragma unroll
            for (int c = 0; c < 8; c++) {
                uint32_t af[4];
                uint32_t qa = (2u * c + kqA) ^ swm;
                ldsm4(af, sb + FQ_OFF + (uint32_t)(w * 16 + rA) * 256 + qa * 16);
#pragma unroll
                for (int p = 0; p < 4; p++) {
                    uint32_t bf[4];
                    uint32_t qb = (2u * c + kqB) ^ swm;
                    ldsm4(bf, kbuf + (uint32_t)(p * 16 + rB) * 256 + qb * 16);
                    mma_f16(sf[2 * p],     af, bf[0], bf[1]);
                    mma_f16(sf[2 * p + 1], af, bf[2], bf[3]);
                }
            }

#pragma unroll
            for (int n = 0; n < 8; n++)
#pragma unroll
                for (int j = 0; j < 4; j++) sf[n][j] *= scale;

            if (k0 + FBN - 1 > q0 + w * 16) {
#pragma unroll
                for (int n = 0; n < 8; n++) {
                    int col = k0 + n * 8 + qw * 2;
                    if (col > row0g)     sf[n][0] = -1e30f;
                    if (col + 1 > row0g) sf[n][1] = -1e30f;
                    if (col > row1g)     sf[n][2] = -1e30f;
                    if (col + 1 > row1g) sf[n][3] = -1e30f;
                }
            }

            // Online softmax (rows g and g+8 of the warp band)
            float mx0 = -1e30f, mx1 = -1e30f;
#pragma unroll
            for (int n = 0; n < 8; n++) {
                mx0 = fmaxf(mx0, fmaxf(sf[n][0], sf[n][1]));
                mx1 = fmaxf(mx1, fmaxf(sf[n][2], sf[n][3]));
            }
            mx0 = fmaxf(mx0, __shfl_xor_sync(0xffffffffu, mx0, 1));
            mx0 = fmaxf(mx0, __shfl_xor_sync(0xffffffffu, mx0, 2));
            mx1 = fmaxf(mx1, __shfl_xor_sync(0xffffffffu, mx1, 1));
            mx1 = fmaxf(mx1, __shfl_xor_sync(0xffffffffu, mx1, 2));
            const float mn0 = fmaxf(mr0, mx0);
            const float mn1 = fmaxf(mr1, mx1);
            const float cor0 = __expf(mr0 - mn0);
            const float cor1 = __expf(mr1 - mn1);
            float rs0 = 0.0f, rs1 = 0.0f;
#pragma unroll
            for (int n = 0; n < 8; n++) {
                sf[n][0] = __expf(sf[n][0] - mn0);
                sf[n][1] = __expf(sf[n][1] - mn0);
                sf[n][2] = __expf(sf[n][2] - mn1);
                sf[n][3] = __expf(sf[n][3] - mn1);
                rs0 += sf[n][0] + sf[n][1];
                rs1 += sf[n][2] + sf[n][3];
            }
            rs0 += __shfl_xor_sync(0xffffffffu, rs0, 1);
            rs0 += __shfl_xor_sync(0xffffffffu, rs0, 2);
            rs1 += __shfl_xor_sync(0xffffffffu, rs1, 1);
            rs1 += __shfl_xor_sync(0xffffffffu, rs1, 2);
            lr0 = lr0 * cor0 + rs0;  mr0 = mn0;
            lr1 = lr1 * cor1 + rs1;  mr1 = mn1;
#pragma unroll
            for (int n = 0; n < 16; n++) {
                o_acc[n][0] *= cor0; o_acc[n][1] *= cor0;
                o_acc[n][2] *= cor1; o_acc[n][3] *= cor1;
            }

            // O += P * V : P stays in registers (C-frag == A-frag layout);
            // V via trans-ldmatrix from row-major [s][dh] tile.
#pragma unroll
            for (int c = 0; c < 4; c++) {
                uint32_t af[4];
                af[0] = packh2(sf[2 * c][0],     sf[2 * c][1]);
                af[1] = packh2(sf[2 * c][2],     sf[2 * c][3]);
                af[2] = packh2(sf[2 * c + 1][0], sf[2 * c + 1][1]);
                af[3] = packh2(sf[2 * c + 1][2], sf[2 * c + 1][3]);
                const int rowv = c * 16 + rV;
#pragma unroll
                for (int p = 0; p < 8; p++) {
                    uint32_t bf[4];
                    uint32_t qd = ((uint32_t)(2 * p + nqV)) ^ (uint32_t)(rowv & 7);
                    ldsm4t(bf, vbuf + (uint32_t)rowv * 256 + qd * 16);
                    mma_f16(o_acc[2 * p],     af, bf[0], bf[1]);
                    mma_f16(o_acc[2 * p + 1], af, bf[2], bf[3]);
                }
            }
        }
    }

    // Epilogue: normalize + write half (GEMM2 consumes directly)
    const float inv0 = 1.0f / lr0;
    const float inv1 = 1.0f / lr1;
#pragma unroll
    for (int n = 0; n < 16; n++) {
        const int col = h * DHEAD + n * 8 + qw * 2;
        __half* p0 = out + (size_t)((size_t)b * S_LEN + row0g) * D_MODEL + col;
        __half* p1 = out + (size_t)((size_t)b * S_LEN + row1g) * D_MODEL + col;
        *(uint32_t*)p0 = packh2(o_acc[n][0] * inv0, o_acc[n][1] * inv0);
        *(uint32_t*)p1 = packh2(o_acc[n][2] * inv1, o_acc[n][3] * inv1);
    }
}

// ---------------------------------------------------------------------------
extern "C" void kernel_launch(void* const* d_in, const int* in_sizes, int n_in,
                              void* d_out, int out_size) {
    const float* x     = (const float*)d_in[0];  // [B,S,D]
    const float* w_in  = (const float*)d_in[1];  // [3*H*DH, D]
    const float* w_out = (const float*)d_in[2];  // [D, H*DH]
    float* out = (float*)d_out;                  // [B,S,D]

    __half *qkv, *attn, *xh, *winh, *wouth;
    cudaGetSymbolAddress((void**)&qkv, g_qkv);
    cudaGetSymbolAddress((void**)&attn, g_attn);
    cudaGetSymbolAddress((void**)&xh, g_xh);
    cudaGetSymbolAddress((void**)&winh, g_winh);
    cudaGetSymbolAddress((void**)&wouth, g_wouth);

    cudaFuncSetAttribute(gemm_mma<1>, cudaFuncAttributeMaxDynamicSharedMemorySize,
                         GEMM_SMEM);
    cudaFuncSetAttribute(gemm_mma<0>, cudaFuncAttributeMaxDynamicSharedMemorySize,
                         GEMM_SMEM);
    cudaFuncSetAttribute(flash_attn_mma, cudaFuncAttributeMaxDynamicSharedMemorySize,
                         FA_SMEM);

    // 0) fp16-convert all GEMM operands (single launch)
    const int n4x = M_TOK * D_MODEL / 4;
    const int n4wi = E3 * D_MODEL / 4;
    const int n4wo = D_MODEL * D_MODEL / 4;
    const int n4tot = n4x + n4wi + n4wo;
    cvt_half3<<<(n4tot + 255) / 256, 256>>>(x, xh, n4x, w_in, winh, n4wi,
                                            w_out, wouth, n4wo);

    // 1) QKV projection (half output)
    dim3 g1(E3 / 128, M_TOK / 128);
    gemm_mma<1><<<g1, 128, GEMM_SMEM>>>(xh, winh, qkv, M_TOK, E3, D_MODEL);

    // 2) Causal flash attention (register-P, trans-V); half output
    dim3 g2(S_LEN / FBM, BATCH * NH);
    flash_attn_mma<<<g2, 256, FA_SMEM>>>(qkv, attn);

    // 3) Output projection (fp32 output)
    dim3 g3(D_MODEL / 128, M_TOK / 128);
    gemm_mma<0><<<g3, 128, GEMM_SMEM>>>(attn, wouth, out, M_TOK, D_MODEL, D_MODEL);
}